// round 10
// baseline (speedup 1.0000x reference)
#include <cuda_runtime.h>
#include <cuda_fp16.h>
#include <cstdint>
#include <cmath>

// scratch: mid tensor x [4,128,256,256] fp16
static __device__ __align__(16) __half g_xmid[(size_t)4 * 128 * 256 * 256];

// ---------------------------------------------------------------------------
// f32x2 packed helpers
// ---------------------------------------------------------------------------
__device__ __forceinline__ unsigned long long pack2(float lo, float hi)
{
    unsigned long long r;
    asm("mov.b64 %0, {%1, %2};" : "=l"(r) : "f"(lo), "f"(hi));
    return r;
}
__device__ __forceinline__ void unpack2(unsigned long long v, float& lo, float& hi)
{
    asm("mov.b64 {%0, %1}, %2;" : "=f"(lo), "=f"(hi) : "l"(v));
}
__device__ __forceinline__ unsigned long long fma2(unsigned long long a,
                                                   unsigned long long b,
                                                   unsigned long long c)
{
    unsigned long long d;
    asm("fma.rn.f32x2 %0, %1, %2, %3;" : "=l"(d) : "l"(a), "l"(b), "l"(c));
    return d;
}

// ---------------------------------------------------------------------------
// 8-point complex FFT (single thread). s=+1 forward, s=-1 inverse, NO scaling.
// ---------------------------------------------------------------------------
__device__ __forceinline__ void cfft8(float zr[8], float zi[8], const float s)
{
    const float cc = 0.70710678118654752440f;
    float t0r = zr[0] + zr[4], t0i = zi[0] + zi[4];
    float t1r = zr[0] - zr[4], t1i = zi[0] - zi[4];
    float t2r = zr[2] + zr[6], t2i = zi[2] + zi[6];
    float t3r = zr[2] - zr[6], t3i = zi[2] - zi[6];
    float E0r = t0r + t2r, E0i = t0i + t2i;
    float E2r = t0r - t2r, E2i = t0i - t2i;
    float E1r = t1r + s * t3i, E1i = t1i - s * t3r;
    float E3r = t1r - s * t3i, E3i = t1i + s * t3r;
    float u0r = zr[1] + zr[5], u0i = zi[1] + zi[5];
    float u1r = zr[1] - zr[5], u1i = zi[1] - zi[5];
    float u2r = zr[3] + zr[7], u2i = zi[3] + zi[7];
    float u3r = zr[3] - zr[7], u3i = zi[3] - zi[7];
    float O0r = u0r + u2r, O0i = u0i + u2i;
    float O2r = u0r - u2r, O2i = u0i - u2i;
    float O1r = u1r + s * u3i, O1i = u1i - s * u3r;
    float O3r = u1r - s * u3i, O3i = u1i + s * u3r;
    float T0r = O0r, T0i = O0i;
    float T1r = cc * (O1r + s * O1i), T1i = cc * (O1i - s * O1r);
    float T2r = s * O2i,              T2i = -s * O2r;
    float T3r = cc * (s * O3i - O3r), T3i = -cc * (O3i + s * O3r);
    zr[0] = E0r + T0r; zi[0] = E0i + T0i;
    zr[4] = E0r - T0r; zi[4] = E0i - T0i;
    zr[1] = E1r + T1r; zi[1] = E1i + T1i;
    zr[5] = E1r - T1r; zi[5] = E1i - T1i;
    zr[2] = E2r + T2r; zi[2] = E2i + T2i;
    zr[6] = E2r - T2r; zi[6] = E2i - T2i;
    zr[3] = E3r + T3r; zi[3] = E3i + T3i;
    zr[7] = E3r - T3r; zi[7] = E3i - T3i;
}

// ---------------------------------------------------------------------------
// Kernel F4 (512 threads, 4 patch-pairs per block) — unchanged from r9 winner.
// ---------------------------------------------------------------------------
__global__ void __launch_bounds__(512, 1) kF4(const float* __restrict__ img,
                                              const float* __restrict__ evt,
                                              const float* __restrict__ w_img,
                                              const float* __restrict__ w_evt,
                                              const float* __restrict__ filt)
{
    extern __shared__ float sm[];
    float*  sWT   = sm;                                    // [64][256]
    float*  sFilt = sm + 16384;                            // [128][41]
    float*  sIn   = sm + 21632;                            // [2][64][128]
    __half* sMidH = reinterpret_cast<__half*>(sm + 38016); // [256][136]

    const int tid = threadIdx.x;
    const int qx = blockIdx.x, ph = blockIdx.y, b = blockIdx.z;

    const float4* img4 = reinterpret_cast<const float4*>(img);
    const float4* evt4 = reinterpret_cast<const float4*>(evt);

    for (int i = tid; i < 64 * 128; i += 512) {
        int k = i >> 7, o = i & 127;
        sWT[k * 256 + o]       = w_img[o * 64 + k];
        sWT[k * 256 + 128 + o] = w_evt[o * 64 + k];
    }
    for (int i = tid; i < 128 * 40; i += 512) {
        int o = i / 40, j = i - o * 40;
        sFilt[o * 41 + j] = filt[i];
    }
    {
        const int pw16 = qx * 4;
        for (int i = tid; i < 64 * 32; i += 512) {
            int c = i >> 5, q4 = i & 31;
            int r = q4 >> 2, xx = q4 & 3;
            int g4 = (((b * 64 + c) * 256 + ph * 8 + r) * 256 + pw16 * 16) / 4 + xx;
            *reinterpret_cast<float4*>(&sIn[c * 128 + q4 * 4])        = img4[g4];
            *reinterpret_cast<float4*>(&sIn[8192 + c * 128 + q4 * 4]) = evt4[g4];
        }
    }
    __syncthreads();

    const int rb = tid >> 4, cb = tid & 15;
    const int r0 = rb * 8, c0 = cb * 8;
    const float* pin = sIn + ((r0 >= 128) ? 8192 : 0);

    const int lane = tid & 31;
    const int w    = tid >> 5;
    const int h    = lane >> 4;
    const int item = w * 16 + (lane & 15);
    const int o    = item & 127;
    const int pp   = item >> 7;
    const bool hB  = (h == 1);
    const float C7 = 0.70710678118654752440f;
    const __half* rowI = sMidH + o * 136 + pp * 8;
    const __half* rowE = sMidH + (128 + o) * 136 + pp * 8;
    const float* fo = sFilt + o * 41;

    for (int it = 0; it < 4; it++) {
        const int pw16 = qx * 4 + it;

        unsigned long long acc[32];
#pragma unroll
        for (int i = 0; i < 32; i++) acc[i] = 0ULL;
#pragma unroll 4
        for (int k = 0; k < 64; k++) {
            float4 w0 = *reinterpret_cast<const float4*>(&sWT[k * 256 + r0]);
            float4 w1 = *reinterpret_cast<const float4*>(&sWT[k * 256 + r0 + 4]);
            ulonglong2 xa = *reinterpret_cast<const ulonglong2*>(&pin[k * 128 + c0]);
            ulonglong2 xb = *reinterpret_cast<const ulonglong2*>(&pin[k * 128 + c0 + 4]);
            unsigned long long xv[4] = {xa.x, xa.y, xb.x, xb.y};
            float wf[8] = {w0.x, w0.y, w0.z, w0.w, w1.x, w1.y, w1.z, w1.w};
#pragma unroll
            for (int i = 0; i < 8; i++) {
                unsigned long long wp = pack2(wf[i], wf[i]);
#pragma unroll
                for (int j = 0; j < 4; j++)
                    acc[i * 4 + j] = fma2(wp, xv[j], acc[i * 4 + j]);
            }
        }
        __syncthreads();

#pragma unroll
        for (int i = 0; i < 8; i++) {
            __half2 hh[4];
#pragma unroll
            for (int j = 0; j < 4; j++) {
                float lo, hi;
                unpack2(acc[i * 4 + j], lo, hi);
                hh[j] = __floats2half2_rn(lo, hi);
            }
            *reinterpret_cast<uint4*>(&sMidH[(r0 + i) * 136 + c0]) =
                *reinterpret_cast<uint4*>(hh);
        }
        if (it < 3) {
            const int pwn = pw16 + 1;
            for (int i = tid; i < 64 * 32; i += 512) {
                int c = i >> 5, q4 = i & 31;
                int r = q4 >> 2, xx = q4 & 3;
                int g4 = (((b * 64 + c) * 256 + ph * 8 + r) * 256 + pwn * 16) / 4 + xx;
                *reinterpret_cast<float4*>(&sIn[c * 128 + q4 * 4])        = img4[g4];
                *reinterpret_cast<float4*>(&sIn[8192 + c * 128 + q4 * 4]) = evt4[g4];
            }
        }
        __syncthreads();

        float Zr[32], Zi[32];

#pragma unroll
        for (int j = 0; j < 4; j++) {
            const int R = h * 4 + j;
            uint4 ra = *reinterpret_cast<const uint4*>(rowI + R * 16);
            uint4 rb2 = *reinterpret_cast<const uint4*>(rowE + R * 16);
            const __half2* ha = reinterpret_cast<const __half2*>(&ra);
            const __half2* hb = reinterpret_cast<const __half2*>(&rb2);
            float zr[8], zi[8];
#pragma unroll
            for (int t = 0; t < 4; t++) {
                float2 fa = __half22float2(ha[t]);
                float2 fb = __half22float2(hb[t]);
                zr[2 * t] = fa.x; zr[2 * t + 1] = fa.y;
                zi[2 * t] = fb.x; zi[2 * t + 1] = fb.y;
            }
            cfft8(zr, zi, 1.0f);
#pragma unroll
            for (int c = 0; c < 8; c++) { Zr[j * 8 + c] = zr[c]; Zi[j * 8 + c] = zi[c]; }
        }

#pragma unroll
        for (int c = 0; c < 8; c++) {
            float lr[4], li[4], rr[4], ri[4];
#pragma unroll
            for (int j = 0; j < 4; j++) { lr[j] = Zr[j * 8 + c]; li[j] = Zi[j * 8 + c]; }
#pragma unroll
            for (int j = 0; j < 4; j++) {
                rr[j] = __shfl_xor_sync(0xffffffffu, lr[j], 16);
                ri[j] = __shfl_xor_sync(0xffffffffu, li[j], 16);
            }
            float tr[4], ti[4];
            if (!hB) {
#pragma unroll
                for (int j = 0; j < 4; j++) { tr[j] = lr[j] + rr[j]; ti[j] = li[j] + ri[j]; }
            } else {
                float dr[4], di[4];
#pragma unroll
                for (int j = 0; j < 4; j++) { dr[j] = rr[j] - lr[j]; di[j] = ri[j] - li[j]; }
                tr[0] = dr[0];               ti[0] = di[0];
                tr[1] = C7 * (dr[1] + di[1]); ti[1] = C7 * (di[1] - dr[1]);
                tr[2] = di[2];               ti[2] = -dr[2];
                tr[3] = C7 * (di[3] - dr[3]); ti[3] = -C7 * (dr[3] + di[3]);
            }
            float s0r = tr[0] + tr[2], s0i = ti[0] + ti[2];
            float s1r = tr[0] - tr[2], s1i = ti[0] - ti[2];
            float s2r = tr[1] + tr[3], s2i = ti[1] + ti[3];
            float s3r = tr[1] - tr[3], s3i = ti[1] - ti[3];
            Zr[0 * 8 + c] = s0r + s2r; Zi[0 * 8 + c] = s0i + s2i;
            Zr[1 * 8 + c] = s1r + s3i; Zi[1 * 8 + c] = s1i - s3r;
            Zr[2 * 8 + c] = s0r - s2r; Zi[2 * 8 + c] = s0i - s2i;
            Zr[3 * 8 + c] = s1r - s3i; Zi[3 * 8 + c] = s1i + s3r;
        }

        const int vv[5] = {0, 4, 1, 2, 3};
        const int mm[5] = {0, 4, 7, 6, 5};
#pragma unroll
        for (int pidx = 0; pidx < 5; pidx++) {
            const int v = vv[pidx], m = mm[pidx];
            float xr[4], xi[4];
#pragma unroll
            for (int k = 0; k < 4; k++) {
                const int u  = 2 * k + h;
                const int kn = hB ? (3 - k) : ((4 - k) & 3);
                float pr = Zr[k * 8 + v],  pi_ = Zi[k * 8 + v];
                float qr = Zr[kn * 8 + m], qi  = Zi[kn * 8 + m];
                float Ir = 0.5f * (pr + qr), Ii = 0.5f * (pi_ - qi);
                float f  = fo[u * 5 + v];
                float Er = 0.5f * f * (pi_ + qi), Ei = 0.5f * f * (qr - pr);
                float ar = Ir + 1.0f;
                xr[k] = ar * Er - Ii * Ei;
                xi[k] = ar * Ei + Ii * Er;
            }
            float s0r = xr[0] + xr[2], s0i = xi[0] + xi[2];
            float s1r = xr[0] - xr[2], s1i = xi[0] - xi[2];
            float s2r = xr[1] + xr[3], s2i = xi[1] + xi[3];
            float s3r = xr[1] - xr[3], s3i = xi[1] - xi[3];
            float gr[4], gi[4];
            gr[0] = s0r + s2r; gi[0] = s0i + s2i;
            gr[1] = s1r - s3i; gi[1] = s1i + s3r;
            gr[2] = s0r - s2r; gi[2] = s0i - s2i;
            gr[3] = s1r + s3i; gi[3] = s1i - s3r;
            float hr[4], hi[4];
#pragma unroll
            for (int j = 0; j < 4; j++) {
                hr[j] = __shfl_xor_sync(0xffffffffu, gr[j], 16);
                hi[j] = __shfl_xor_sync(0xffffffffu, gi[j], 16);
            }
            if (!hB) {
                Zr[0*8+v] = gr[0] + hr[0];                 Zi[0*8+v] = gi[0] + hi[0];
                Zr[1*8+v] = gr[1] + C7 * (hr[1] - hi[1]);  Zi[1*8+v] = gi[1] + C7 * (hr[1] + hi[1]);
                Zr[2*8+v] = gr[2] - hi[2];                 Zi[2*8+v] = gi[2] + hr[2];
                Zr[3*8+v] = gr[3] - C7 * (hr[3] + hi[3]);  Zi[3*8+v] = gi[3] + C7 * (hr[3] - hi[3]);
            } else {
                Zr[0*8+v] = hr[0] - gr[0];                 Zi[0*8+v] = hi[0] - gi[0];
                Zr[1*8+v] = hr[1] - C7 * (gr[1] - gi[1]);  Zi[1*8+v] = hi[1] - C7 * (gr[1] + gi[1]);
                Zr[2*8+v] = hr[2] + gi[2];                 Zi[2*8+v] = hi[2] - gr[2];
                Zr[3*8+v] = hr[3] + C7 * (gr[3] + gi[3]);  Zi[3*8+v] = hi[3] - C7 * (gr[3] - gi[3]);
            }
        }

        __half* outp = g_xmid + (((size_t)(b * 128 + o) * 256 + ph * 8) * 256
                                 + pw16 * 16 + pp * 8);
        const float sc = 1.0f / 64.0f;
#pragma unroll
        for (int j = 0; j < 4; j++) {
            const int R = h * 4 + j;
            float zr[8], zi[8];
#pragma unroll
            for (int v = 0; v < 5; v++) { zr[v] = Zr[j * 8 + v]; zi[v] = Zi[j * 8 + v]; }
            zr[5] = Zr[j * 8 + 3]; zi[5] = -Zi[j * 8 + 3];
            zr[6] = Zr[j * 8 + 2]; zi[6] = -Zi[j * 8 + 2];
            zr[7] = Zr[j * 8 + 1]; zi[7] = -Zi[j * 8 + 1];
            cfft8(zr, zi, -1.0f);
            __half2 hh[4];
#pragma unroll
            for (int t = 0; t < 4; t++)
                hh[t] = __floats2half2_rn(zr[2 * t] * sc, zr[2 * t + 1] * sc);
            *reinterpret_cast<uint4*>(outp + (size_t)R * 256) =
                *reinterpret_cast<uint4*>(hh);
        }
    }
}

// ---------------------------------------------------------------------------
// Kernel DO (512 threads): fused depthwise 3x3 + GELU gate + out 1x1 GEMM.
// Block = 16x16 pixel tile of one batch. No gate round trip through DRAM.
// smem (floats):
//   sHalo (half) [128][18][20] = 23040 fl
//   sG    [64][264]            = 16896 fl   (gate, fp32)
//   sWoT  [64][64]             =  4096 fl
//   sWdw  [128][9]             =  1152 fl
// total 45184 fl = 180,736 B -> 1 block/SM
// ---------------------------------------------------------------------------
__global__ void __launch_bounds__(512, 1) kDO(const float* __restrict__ w_dw,
                                              const float* __restrict__ w_out,
                                              float* __restrict__ out)
{
    extern __shared__ float sm[];
    __half* sHalo = reinterpret_cast<__half*>(sm);  // [128][18][20]
    float*  sG    = sm + 23040;                     // [64][264]
    float*  sWoT  = sm + 39936;                     // [64][64]
    float*  sWdw  = sm + 44032;                     // [128][9]

    const int tid = threadIdx.x;
    const int x0 = blockIdx.x * 16, y0 = blockIdx.y * 16;
    const int b  = blockIdx.z;

    // stage weights
    for (int i = tid; i < 64 * 64; i += 512) {
        int k = i >> 6, o = i & 63;
        sWoT[k * 64 + o] = w_out[o * 64 + k];
    }
    for (int i = tid; i < 128 * 9; i += 512) sWdw[i] = w_dw[i];

    // stage halo: 128 channels x 18 x 18 (zero-padded), fp16 passthrough
    {
        const __half zero = __float2half(0.f);
        const __half* src = g_xmid + (size_t)b * 128 * 65536;
        for (int i = tid; i < 128 * 324; i += 512) {
            int ch = i / 324, r2 = i - ch * 324;
            int y = r2 / 18, x = r2 - y * 18;
            int gy = y0 + y - 1, gx = x0 + x - 1;
            __half v = zero;
            if (gy >= 0 && gy < 256 && gx >= 0 && gx < 256)
                v = src[(size_t)ch * 65536 + (size_t)gy * 256 + gx];
            sHalo[ch * 360 + y * 20 + x] = v;
        }
    }
    __syncthreads();

    // depthwise 3x3 + exact GELU gate -> sG[c][px]
    {
        const int px = tid & 255;            // pixel within 16x16 tile
        const int py = px >> 4, pxx = px & 15;
        const int cg = tid >> 8;             // 0: c 0..31, 1: c 32..63
#pragma unroll 4
        for (int ci = 0; ci < 32; ci++) {
            const int c = cg * 32 + ci;
            const __half* h1 = sHalo + c * 360;
            const __half* h2 = sHalo + (c + 64) * 360;
            float a = 0.f, bb = 0.f;
#pragma unroll
            for (int dy = 0; dy < 3; dy++)
#pragma unroll
                for (int dx = 0; dx < 3; dx++) {
                    const int hoff = (py + dy) * 20 + pxx + dx;
                    a  = fmaf(__half2float(h1[hoff]), sWdw[c * 9 + dy * 3 + dx], a);
                    bb = fmaf(__half2float(h2[hoff]), sWdw[(c + 64) * 9 + dy * 3 + dx], bb);
                }
            float gl = 0.5f * a * (1.0f + erff(a * 0.70710678118654752f));
            sG[c * 264 + px] = gl * bb;
        }
    }
    __syncthreads();

    // out GEMM: 64 oc x 256 px, k = 64; warp = 4 oc x 256 px, thread 4x8
    {
        const int ob  = tid >> 5, pb = tid & 31;
        const int oc0 = ob * 4,  p0 = pb * 8;
        unsigned long long acc[16];
#pragma unroll
        for (int i = 0; i < 16; i++) acc[i] = 0ULL;
#pragma unroll 8
        for (int k = 0; k < 64; k++) {
            float4 w0 = *reinterpret_cast<const float4*>(&sWoT[k * 64 + oc0]);
            ulonglong2 ga = *reinterpret_cast<const ulonglong2*>(&sG[k * 264 + p0]);
            ulonglong2 gb = *reinterpret_cast<const ulonglong2*>(&sG[k * 264 + p0 + 4]);
            unsigned long long gv[4] = {ga.x, ga.y, gb.x, gb.y};
            float wf[4] = {w0.x, w0.y, w0.z, w0.w};
#pragma unroll
            for (int i = 0; i < 4; i++) {
                unsigned long long wp = pack2(wf[i], wf[i]);
#pragma unroll
                for (int j = 0; j < 4; j++)
                    acc[i * 4 + j] = fma2(wp, gv[j], acc[i * 4 + j]);
            }
        }
        const int wy = y0 + (p0 >> 4);
        const int wx = x0 + (p0 & 15);
#pragma unroll
        for (int i = 0; i < 4; i++) {
            float v[8];
#pragma unroll
            for (int j = 0; j < 4; j++) unpack2(acc[i * 4 + j], v[2 * j], v[2 * j + 1]);
            size_t ga = ((size_t)(b * 64 + oc0 + i) * 256 + wy) * 256 + wx;
            float4 q0 = {v[0], v[1], v[2], v[3]};
            float4 q1 = {v[4], v[5], v[6], v[7]};
            *reinterpret_cast<float4*>(&out[ga])     = q0;
            *reinterpret_cast<float4*>(&out[ga + 4]) = q1;
        }
    }
}

// ---------------------------------------------------------------------------
extern "C" void kernel_launch(void* const* d_in, const int* in_sizes, int n_in,
                              void* d_out, int out_size)
{
    const float* img   = (const float*)d_in[0];
    const float* evt   = (const float*)d_in[1];
    const float* w_img = (const float*)d_in[2];
    const float* w_evt = (const float*)d_in[3];
    const float* w_dw  = (const float*)d_in[4];
    const float* filt  = (const float*)d_in[5];
    const float* w_out = (const float*)d_in[6];
    float* out = (float*)d_out;

    const int smemF = 55424 * 4;   // 221,696 B
    const int smemD = 45184 * 4;   // 180,736 B
    cudaFuncSetAttribute(kF4, cudaFuncAttributeMaxDynamicSharedMemorySize, smemF);
    cudaFuncSetAttribute(kDO, cudaFuncAttributeMaxDynamicSharedMemorySize, smemD);

    kF4<<<dim3(4, 32, 4), 512, smemF>>>(img, evt, w_img, w_evt, filt);
    kDO<<<dim3(16, 16, 4), 512, smemD>>>(w_dw, w_out, out);
}

// round 11
// speedup vs baseline: 1.2577x; 1.2577x over previous
#include <cuda_runtime.h>
#include <cuda_fp16.h>
#include <cstdint>
#include <cmath>

// scratch: mid tensor x [4,128,256,256] fp16, gated tensor [4,64,256,256] fp16
static __device__ __align__(16) __half g_xmid[(size_t)4 * 128 * 256 * 256];
static __device__ __align__(16) __half g_gate[(size_t)4 * 64 * 256 * 256];

// ---------------------------------------------------------------------------
// f32x2 packed helpers
// ---------------------------------------------------------------------------
__device__ __forceinline__ unsigned long long pack2(float lo, float hi)
{
    unsigned long long r;
    asm("mov.b64 %0, {%1, %2};" : "=l"(r) : "f"(lo), "f"(hi));
    return r;
}
__device__ __forceinline__ void unpack2(unsigned long long v, float& lo, float& hi)
{
    asm("mov.b64 {%0, %1}, %2;" : "=f"(lo), "=f"(hi) : "l"(v));
}
__device__ __forceinline__ unsigned long long fma2(unsigned long long a,
                                                   unsigned long long b,
                                                   unsigned long long c)
{
    unsigned long long d;
    asm("fma.rn.f32x2 %0, %1, %2, %3;" : "=l"(d) : "l"(a), "l"(b), "l"(c));
    return d;
}

// ---------------------------------------------------------------------------
// 8-point complex FFT (single thread). s=+1 forward, s=-1 inverse, NO scaling.
// ---------------------------------------------------------------------------
__device__ __forceinline__ void cfft8(float zr[8], float zi[8], const float s)
{
    const float cc = 0.70710678118654752440f;
    float t0r = zr[0] + zr[4], t0i = zi[0] + zi[4];
    float t1r = zr[0] - zr[4], t1i = zi[0] - zi[4];
    float t2r = zr[2] + zr[6], t2i = zi[2] + zi[6];
    float t3r = zr[2] - zr[6], t3i = zi[2] - zi[6];
    float E0r = t0r + t2r, E0i = t0i + t2i;
    float E2r = t0r - t2r, E2i = t0i - t2i;
    float E1r = t1r + s * t3i, E1i = t1i - s * t3r;
    float E3r = t1r - s * t3i, E3i = t1i + s * t3r;
    float u0r = zr[1] + zr[5], u0i = zi[1] + zi[5];
    float u1r = zr[1] - zr[5], u1i = zi[1] - zi[5];
    float u2r = zr[3] + zr[7], u2i = zi[3] + zi[7];
    float u3r = zr[3] - zr[7], u3i = zi[3] - zi[7];
    float O0r = u0r + u2r, O0i = u0i + u2i;
    float O2r = u0r - u2r, O2i = u0i - u2i;
    float O1r = u1r + s * u3i, O1i = u1i - s * u3r;
    float O3r = u1r - s * u3i, O3i = u1i + s * u3r;
    float T0r = O0r, T0i = O0i;
    float T1r = cc * (O1r + s * O1i), T1i = cc * (O1i - s * O1r);
    float T2r = s * O2i,              T2i = -s * O2r;
    float T3r = cc * (s * O3i - O3r), T3i = -cc * (O3i + s * O3r);
    zr[0] = E0r + T0r; zi[0] = E0i + T0i;
    zr[4] = E0r - T0r; zi[4] = E0i - T0i;
    zr[1] = E1r + T1r; zi[1] = E1i + T1i;
    zr[5] = E1r - T1r; zi[5] = E1i - T1i;
    zr[2] = E2r + T2r; zi[2] = E2i + T2i;
    zr[6] = E2r - T2r; zi[6] = E2i - T2i;
    zr[3] = E3r + T3r; zi[3] = E3i + T3i;
    zr[7] = E3r - T3r; zi[7] = E3i - T3i;
}

// tile decode: t in [0, 2048): b = t>>9, ph = (t>>4)&31, pw16 = t&15
#define NT_TILES 2048

// ---------------------------------------------------------------------------
// Kernel F5 (512 threads, persistent-strided over 2048 patch-pair tiles):
// same pipeline as the r9 winner (GEMM -> spill fp16 -> cooperative register
// FFT) but each block loops tiles with stride gridDim.x, staging weights and
// filter ONCE, and double-buffering pixel loads across iterations.
// smem: sWT 16384 fl | sFilt 5248 fl | sIn 16384 fl | sMid(half) 17408 fl
// ---------------------------------------------------------------------------
__global__ void __launch_bounds__(512, 1) kF5(const float* __restrict__ img,
                                              const float* __restrict__ evt,
                                              const float* __restrict__ w_img,
                                              const float* __restrict__ w_evt,
                                              const float* __restrict__ filt)
{
    extern __shared__ float sm[];
    float*  sWT   = sm;                                    // [64][256]
    float*  sFilt = sm + 16384;                            // [128][41]
    float*  sIn   = sm + 21632;                            // [2][64][128]
    __half* sMidH = reinterpret_cast<__half*>(sm + 38016); // [256][136]

    const int tid    = threadIdx.x;
    const int stride = gridDim.x;

    const float4* img4 = reinterpret_cast<const float4*>(img);
    const float4* evt4 = reinterpret_cast<const float4*>(evt);

    // one-time prologue: weights (transposed) + filter
    for (int i = tid; i < 64 * 128; i += 512) {
        int k = i >> 7, o = i & 127;
        sWT[k * 256 + o]       = w_img[o * 64 + k];
        sWT[k * 256 + 128 + o] = w_evt[o * 64 + k];
    }
    for (int i = tid; i < 128 * 40; i += 512) {
        int o = i / 40, j = i - o * 40;
        sFilt[o * 41 + j] = filt[i];
    }

    int t = blockIdx.x;
    if (t < NT_TILES) {
        // pixels for first tile
        const int b0 = t >> 9, ph0 = (t >> 4) & 31, pw0 = t & 15;
        for (int i = tid; i < 64 * 32; i += 512) {
            int c = i >> 5, q4 = i & 31;
            int r = q4 >> 2, xx = q4 & 3;
            int g4 = (((b0 * 64 + c) * 256 + ph0 * 8 + r) * 256 + pw0 * 16) / 4 + xx;
            *reinterpret_cast<float4*>(&sIn[c * 128 + q4 * 4])        = img4[g4];
            *reinterpret_cast<float4*>(&sIn[8192 + c * 128 + q4 * 4]) = evt4[g4];
        }
    }
    __syncthreads();

    // GEMM thread tile: 8 slots x 8 px
    const int rb = tid >> 4, cb = tid & 15;
    const int r0 = rb * 8, c0 = cb * 8;
    const float* pin = sIn + ((r0 >= 128) ? 8192 : 0);

    // FFT role: 2 threads per (channel, patch)
    const int lane = tid & 31;
    const int w    = tid >> 5;
    const int h    = lane >> 4;
    const int item = w * 16 + (lane & 15);
    const int o    = item & 127;
    const int pp   = item >> 7;
    const bool hB  = (h == 1);
    const float C7 = 0.70710678118654752440f;
    const __half* rowI = sMidH + o * 136 + pp * 8;
    const __half* rowE = sMidH + (128 + o) * 136 + pp * 8;
    const float* fo = sFilt + o * 41;

    while (t < NT_TILES) {
        const int b    = t >> 9;
        const int ph   = (t >> 4) & 31;
        const int pw16 = t & 15;
        const int tn   = t + stride;

        // ---- GEMM: 256 slots x 128 px, k=64 (f32x2) ----
        unsigned long long acc[32];
#pragma unroll
        for (int i = 0; i < 32; i++) acc[i] = 0ULL;
#pragma unroll 4
        for (int k = 0; k < 64; k++) {
            float4 w0 = *reinterpret_cast<const float4*>(&sWT[k * 256 + r0]);
            float4 w1 = *reinterpret_cast<const float4*>(&sWT[k * 256 + r0 + 4]);
            ulonglong2 xa = *reinterpret_cast<const ulonglong2*>(&pin[k * 128 + c0]);
            ulonglong2 xb = *reinterpret_cast<const ulonglong2*>(&pin[k * 128 + c0 + 4]);
            unsigned long long xv[4] = {xa.x, xa.y, xb.x, xb.y};
            float wf[8] = {w0.x, w0.y, w0.z, w0.w, w1.x, w1.y, w1.z, w1.w};
#pragma unroll
            for (int i = 0; i < 8; i++) {
                unsigned long long wp = pack2(wf[i], wf[i]);
#pragma unroll
                for (int j = 0; j < 4; j++)
                    acc[i * 4 + j] = fma2(wp, xv[j], acc[i * 4 + j]);
            }
        }
        __syncthreads();   // sIn reads done; prev FFT done with sMid

        // ---- spill acc -> sMid fp16 ----
#pragma unroll
        for (int i = 0; i < 8; i++) {
            __half2 hh[4];
#pragma unroll
            for (int j = 0; j < 4; j++) {
                float lo, hi;
                unpack2(acc[i * 4 + j], lo, hi);
                hh[j] = __floats2half2_rn(lo, hi);
            }
            *reinterpret_cast<uint4*>(&sMidH[(r0 + i) * 136 + c0]) =
                *reinterpret_cast<uint4*>(hh);
        }
        // ---- preload pixels for next tile ----
        if (tn < NT_TILES) {
            const int bn = tn >> 9, phn = (tn >> 4) & 31, pwn = tn & 15;
            for (int i = tid; i < 64 * 32; i += 512) {
                int c = i >> 5, q4 = i & 31;
                int r = q4 >> 2, xx = q4 & 3;
                int g4 = (((bn * 64 + c) * 256 + phn * 8 + r) * 256 + pwn * 16) / 4 + xx;
                *reinterpret_cast<float4*>(&sIn[c * 128 + q4 * 4])        = img4[g4];
                *reinterpret_cast<float4*>(&sIn[8192 + c * 128 + q4 * 4]) = evt4[g4];
            }
        }
        __syncthreads();   // sMid + sIn(next) ready

        // ---- cooperative register FFT ----
        float Zr[32], Zi[32];

#pragma unroll
        for (int j = 0; j < 4; j++) {
            const int R = h * 4 + j;
            uint4 ra = *reinterpret_cast<const uint4*>(rowI + R * 16);
            uint4 rb2 = *reinterpret_cast<const uint4*>(rowE + R * 16);
            const __half2* ha = reinterpret_cast<const __half2*>(&ra);
            const __half2* hb = reinterpret_cast<const __half2*>(&rb2);
            float zr[8], zi[8];
#pragma unroll
            for (int tt = 0; tt < 4; tt++) {
                float2 fa = __half22float2(ha[tt]);
                float2 fb = __half22float2(hb[tt]);
                zr[2 * tt] = fa.x; zr[2 * tt + 1] = fa.y;
                zi[2 * tt] = fb.x; zi[2 * tt + 1] = fb.y;
            }
            cfft8(zr, zi, 1.0f);
#pragma unroll
            for (int c = 0; c < 8; c++) { Zr[j * 8 + c] = zr[c]; Zi[j * 8 + c] = zi[c]; }
        }

#pragma unroll
        for (int c = 0; c < 8; c++) {
            float lr[4], li[4], rr[4], ri[4];
#pragma unroll
            for (int j = 0; j < 4; j++) { lr[j] = Zr[j * 8 + c]; li[j] = Zi[j * 8 + c]; }
#pragma unroll
            for (int j = 0; j < 4; j++) {
                rr[j] = __shfl_xor_sync(0xffffffffu, lr[j], 16);
                ri[j] = __shfl_xor_sync(0xffffffffu, li[j], 16);
            }
            float tr[4], ti[4];
            if (!hB) {
#pragma unroll
                for (int j = 0; j < 4; j++) { tr[j] = lr[j] + rr[j]; ti[j] = li[j] + ri[j]; }
            } else {
                float dr[4], di[4];
#pragma unroll
                for (int j = 0; j < 4; j++) { dr[j] = rr[j] - lr[j]; di[j] = ri[j] - li[j]; }
                tr[0] = dr[0];               ti[0] = di[0];
                tr[1] = C7 * (dr[1] + di[1]); ti[1] = C7 * (di[1] - dr[1]);
                tr[2] = di[2];               ti[2] = -dr[2];
                tr[3] = C7 * (di[3] - dr[3]); ti[3] = -C7 * (dr[3] + di[3]);
            }
            float s0r = tr[0] + tr[2], s0i = ti[0] + ti[2];
            float s1r = tr[0] - tr[2], s1i = ti[0] - ti[2];
            float s2r = tr[1] + tr[3], s2i = ti[1] + ti[3];
            float s3r = tr[1] - tr[3], s3i = ti[1] - ti[3];
            Zr[0 * 8 + c] = s0r + s2r; Zi[0 * 8 + c] = s0i + s2i;
            Zr[1 * 8 + c] = s1r + s3i; Zi[1 * 8 + c] = s1i - s3r;
            Zr[2 * 8 + c] = s0r - s2r; Zi[2 * 8 + c] = s0i - s2i;
            Zr[3 * 8 + c] = s1r - s3i; Zi[3 * 8 + c] = s1i + s3r;
        }

        const int vv[5] = {0, 4, 1, 2, 3};
        const int mm[5] = {0, 4, 7, 6, 5};
#pragma unroll
        for (int pidx = 0; pidx < 5; pidx++) {
            const int v = vv[pidx], m = mm[pidx];
            float xr[4], xi[4];
#pragma unroll
            for (int k = 0; k < 4; k++) {
                const int u  = 2 * k + h;
                const int kn = hB ? (3 - k) : ((4 - k) & 3);
                float pr = Zr[k * 8 + v],  pi_ = Zi[k * 8 + v];
                float qr = Zr[kn * 8 + m], qi  = Zi[kn * 8 + m];
                float Ir = 0.5f * (pr + qr), Ii = 0.5f * (pi_ - qi);
                float f  = fo[u * 5 + v];
                float Er = 0.5f * f * (pi_ + qi), Ei = 0.5f * f * (qr - pr);
                float ar = Ir + 1.0f;
                xr[k] = ar * Er - Ii * Ei;
                xi[k] = ar * Ei + Ii * Er;
            }
            float s0r = xr[0] + xr[2], s0i = xi[0] + xi[2];
            float s1r = xr[0] - xr[2], s1i = xi[0] - xi[2];
            float s2r = xr[1] + xr[3], s2i = xi[1] + xi[3];
            float s3r = xr[1] - xr[3], s3i = xi[1] - xi[3];
            float gr[4], gi[4];
            gr[0] = s0r + s2r; gi[0] = s0i + s2i;
            gr[1] = s1r - s3i; gi[1] = s1i + s3r;
            gr[2] = s0r - s2r; gi[2] = s0i - s2i;
            gr[3] = s1r + s3i; gi[3] = s1i - s3r;
            float hr[4], hi[4];
#pragma unroll
            for (int j = 0; j < 4; j++) {
                hr[j] = __shfl_xor_sync(0xffffffffu, gr[j], 16);
                hi[j] = __shfl_xor_sync(0xffffffffu, gi[j], 16);
            }
            if (!hB) {
                Zr[0*8+v] = gr[0] + hr[0];                 Zi[0*8+v] = gi[0] + hi[0];
                Zr[1*8+v] = gr[1] + C7 * (hr[1] - hi[1]);  Zi[1*8+v] = gi[1] + C7 * (hr[1] + hi[1]);
                Zr[2*8+v] = gr[2] - hi[2];                 Zi[2*8+v] = gi[2] + hr[2];
                Zr[3*8+v] = gr[3] - C7 * (hr[3] + hi[3]);  Zi[3*8+v] = gi[3] + C7 * (hr[3] - hi[3]);
            } else {
                Zr[0*8+v] = hr[0] - gr[0];                 Zi[0*8+v] = hi[0] - gi[0];
                Zr[1*8+v] = hr[1] - C7 * (gr[1] - gi[1]);  Zi[1*8+v] = hi[1] - C7 * (gr[1] + gi[1]);
                Zr[2*8+v] = hr[2] + gi[2];                 Zi[2*8+v] = hi[2] - gr[2];
                Zr[3*8+v] = hr[3] + C7 * (gr[3] + gi[3]);  Zi[3*8+v] = hi[3] - C7 * (gr[3] - gi[3]);
            }
        }

        __half* outp = g_xmid + (((size_t)(b * 128 + o) * 256 + ph * 8) * 256
                                 + pw16 * 16 + pp * 8);
        const float sc = 1.0f / 64.0f;
#pragma unroll
        for (int j = 0; j < 4; j++) {
            const int R = h * 4 + j;
            float zr[8], zi[8];
#pragma unroll
            for (int v = 0; v < 5; v++) { zr[v] = Zr[j * 8 + v]; zi[v] = Zi[j * 8 + v]; }
            zr[5] = Zr[j * 8 + 3]; zi[5] = -Zi[j * 8 + 3];
            zr[6] = Zr[j * 8 + 2]; zi[6] = -Zi[j * 8 + 2];
            zr[7] = Zr[j * 8 + 1]; zi[7] = -Zi[j * 8 + 1];
            cfft8(zr, zi, -1.0f);
            __half2 hh[4];
#pragma unroll
            for (int tt = 0; tt < 4; tt++)
                hh[tt] = __floats2half2_rn(zr[2 * tt] * sc, zr[2 * tt + 1] * sc);
            *reinterpret_cast<uint4*>(outp + (size_t)R * 256) =
                *reinterpret_cast<uint4*>(hh);
        }

        t = tn;
    }
}

// ---------------------------------------------------------------------------
// Kernel DW: depthwise 3x3 (SAME) on channel pair (c, c+64), exact GELU gate.
// Reads fp16 xmid, writes fp16 gate. (r9 version, unchanged)
// ---------------------------------------------------------------------------
__global__ void __launch_bounds__(256) kDW(const float* __restrict__ w_dw)
{
    __shared__ float sH[2 * 18 * 68];

    const int tid = threadIdx.x;
    const int b = blockIdx.z >> 6, c = blockIdx.z & 63;
    const int x0 = blockIdx.x * 64, y0 = blockIdx.y * 16;

    float w1[9], w2[9];
#pragma unroll
    for (int j = 0; j < 9; j++) {
        w1[j] = w_dw[c * 9 + j];
        w2[j] = w_dw[(c + 64) * 9 + j];
    }

    const __half* src0 = g_xmid + (size_t)(b * 128 + c) * 65536;
    const __half* src1 = src0 + (size_t)64 * 65536;

    for (int i = tid; i < 18 * 66; i += 256) {
        int y = i / 66, x = i - y * 66;
        int gy = y0 + y - 1, gx = x0 + x - 1;
        float v0 = 0.f, v1 = 0.f;
        if (gy >= 0 && gy < 256 && gx >= 0 && gx < 256) {
            size_t gi = (size_t)gy * 256 + gx;
            v0 = __half2float(src0[gi]);
            v1 = __half2float(src1[gi]);
        }
        sH[y * 68 + x]        = v0;
        sH[1224 + y * 68 + x] = v1;
    }
    __syncthreads();

    const int px = tid & 63, ty = tid >> 6;
    __half* dst = g_gate + (size_t)(b * 64 + c) * 65536;
#pragma unroll
    for (int yy = 0; yy < 4; yy++) {
        int py = ty * 4 + yy;
        float a = 0.f, bb = 0.f;
#pragma unroll
        for (int dy = 0; dy < 3; dy++)
#pragma unroll
            for (int dx = 0; dx < 3; dx++) {
                a  = fmaf(sH[(py + dy) * 68 + px + dx],        w1[dy * 3 + dx], a);
                bb = fmaf(sH[1224 + (py + dy) * 68 + px + dx], w2[dy * 3 + dx], bb);
            }
        float gl = 0.5f * a * (1.0f + erff(a * 0.70710678118654752f));
        dst[(size_t)(y0 + py) * 256 + x0 + px] = __float2half_rn(gl * bb);
    }
}

// ---------------------------------------------------------------------------
// Kernel Out2: persistent 1x1 projection. Each block strides over image rows;
// weights staged ONCE. GEMM 64oc x 256px x 64k, 8x8 f32x2 tiles.
// smem: sG[64][256] fp32 + sWoT[64][64] = 81,920 B (2 blocks/SM)
// ---------------------------------------------------------------------------
__global__ void __launch_bounds__(256, 2) kOut2(const float* __restrict__ w_out,
                                                float* __restrict__ out)
{
    extern __shared__ float sm[];
    float* sG   = sm;          // [64][256]
    float* sWoT = sm + 16384;  // [64][64]

    const int tid    = threadIdx.x;
    const int stride = gridDim.x;

    for (int i = tid; i < 64 * 64; i += 256) {
        int k = i >> 6, o = i & 63;
        sWoT[k * 64 + o] = w_out[o * 64 + k];
    }

    const int ob = tid >> 5, pb = tid & 31;
    const int oc0 = ob * 8, p0 = pb * 8;

    for (int rr = blockIdx.x; rr < 1024; rr += stride) {
        const int b = rr >> 8, y = rr & 255;

        __syncthreads();   // previous GEMM's sG reads done (and weights ready)
        for (int i = tid; i < 2048; i += 256) {   // 64 rows x 32 uint4
            int k = i >> 5, p8 = i & 31;
            uint4 rh = *reinterpret_cast<const uint4*>(
                g_gate + (size_t)(b * 64 + k) * 65536 + (size_t)y * 256 + p8 * 8);
            const __half2* hp = reinterpret_cast<const __half2*>(&rh);
            float v[8];
#pragma unroll
            for (int tt = 0; tt < 4; tt++) {
                float2 f2 = __half22float2(hp[tt]);
                v[2 * tt] = f2.x; v[2 * tt + 1] = f2.y;
            }
            float4 q0 = {v[0], v[1], v[2], v[3]};
            float4 q1 = {v[4], v[5], v[6], v[7]};
            *reinterpret_cast<float4*>(&sG[k * 256 + p8 * 8])     = q0;
            *reinterpret_cast<float4*>(&sG[k * 256 + p8 * 8 + 4]) = q1;
        }
        __syncthreads();

        unsigned long long acc[32];
#pragma unroll
        for (int i = 0; i < 32; i++) acc[i] = 0ULL;
#pragma unroll 8
        for (int k = 0; k < 64; k++) {
            float4 w0 = *reinterpret_cast<const float4*>(&sWoT[k * 64 + oc0]);
            float4 w1 = *reinterpret_cast<const float4*>(&sWoT[k * 64 + oc0 + 4]);
            ulonglong2 ga = *reinterpret_cast<const ulonglong2*>(&sG[k * 256 + p0]);
            ulonglong2 gb = *reinterpret_cast<const ulonglong2*>(&sG[k * 256 + p0 + 4]);
            unsigned long long gv[4] = {ga.x, ga.y, gb.x, gb.y};
            float wf[8] = {w0.x, w0.y, w0.z, w0.w, w1.x, w1.y, w1.z, w1.w};
#pragma unroll
            for (int i = 0; i < 8; i++) {
                unsigned long long wp = pack2(wf[i], wf[i]);
#pragma unroll
                for (int j = 0; j < 4; j++)
                    acc[i * 4 + j] = fma2(wp, gv[j], acc[i * 4 + j]);
            }
        }
#pragma unroll
        for (int i = 0; i < 8; i++) {
            float v[8];
#pragma unroll
            for (int j = 0; j < 4; j++) unpack2(acc[i * 4 + j], v[2 * j], v[2 * j + 1]);
            size_t ga = ((size_t)(b * 64 + oc0 + i) * 256 + y) * 256 + p0;
            float4 q0 = {v[0], v[1], v[2], v[3]};
            float4 q1 = {v[4], v[5], v[6], v[7]};
            *reinterpret_cast<float4*>(&out[ga])     = q0;
            *reinterpret_cast<float4*>(&out[ga + 4]) = q1;
        }
    }
}

// ---------------------------------------------------------------------------
extern "C" void kernel_launch(void* const* d_in, const int* in_sizes, int n_in,
                              void* d_out, int out_size)
{
    const float* img   = (const float*)d_in[0];
    const float* evt   = (const float*)d_in[1];
    const float* w_img = (const float*)d_in[2];
    const float* w_evt = (const float*)d_in[3];
    const float* w_dw  = (const float*)d_in[4];
    const float* filt  = (const float*)d_in[5];
    const float* w_out = (const float*)d_in[6];
    float* out = (float*)d_out;

    const int smemF = 55424 * 4;   // 221,696 B -> 1 block/SM
    const int smemO = 20480 * 4;   //  81,920 B -> 2 blocks/SM
    cudaFuncSetAttribute(kF5,   cudaFuncAttributeMaxDynamicSharedMemorySize, smemF);
    cudaFuncSetAttribute(kOut2, cudaFuncAttributeMaxDynamicSharedMemorySize, smemO);

    kF5<<<296, 512, smemF>>>(img, evt, w_img, w_evt, filt);
    kDW<<<dim3(4, 16, 256), 256>>>(w_dw);
    kOut2<<<296, 256, smemO>>>(w_out, out);
}

// round 12
// speedup vs baseline: 1.3254x; 1.0539x over previous
#include <cuda_runtime.h>
#include <cuda_fp16.h>
#include <cstdint>
#include <cmath>

// scratch: mid tensor x [4,128,256,256] fp16, gated tensor [4,64,256,256] fp16
static __device__ __align__(16) __half g_xmid[(size_t)4 * 128 * 256 * 256];
static __device__ __align__(16) __half g_gate[(size_t)4 * 64 * 256 * 256];

typedef unsigned long long ull;

// ---------------------------------------------------------------------------
// f32x2 packed helpers. Packed complex convention: lo = re, hi = im.
// ---------------------------------------------------------------------------
__device__ __forceinline__ ull pack2(float lo, float hi)
{
    ull r;
    asm("mov.b64 %0, {%1, %2};" : "=l"(r) : "f"(lo), "f"(hi));
    return r;
}
__device__ __forceinline__ void unpack2(ull v, float& lo, float& hi)
{
    asm("mov.b64 {%0, %1}, %2;" : "=f"(lo), "=f"(hi) : "l"(v));
}
__device__ __forceinline__ ull fma2(ull a, ull b, ull c)
{
    ull d;
    asm("fma.rn.f32x2 %0, %1, %2, %3;" : "=l"(d) : "l"(a), "l"(b), "l"(c));
    return d;
}
__device__ __forceinline__ ull cadd(ull a, ull b)
{
    ull d;
    asm("add.rn.f32x2 %0, %1, %2;" : "=l"(d) : "l"(a), "l"(b));
    return d;
}
__device__ __forceinline__ ull cmul2(ull a, ull b)
{
    ull d;
    asm("mul.rn.f32x2 %0, %1, %2;" : "=l"(d) : "l"(a), "l"(b));
    return d;
}
// a - b, exact (multiply by -1 is exact)
__device__ __forceinline__ ull csub(ull a, ull b)
{
    const ull NEG1 = pack2(-1.0f, -1.0f);
    return fma2(NEG1, b, a);
}
__device__ __forceinline__ float fneg(float x)
{
    return __int_as_float(__float_as_int(x) ^ 0x80000000);
}
// conj: flip sign of imag (hi) half
__device__ __forceinline__ ull cconj(ull v) { return v ^ 0x8000000000000000ULL; }
// (-i)*v = (im, -re)
__device__ __forceinline__ ull mneg_i(ull v)
{
    float r, i; unpack2(v, r, i);
    return pack2(i, fneg(r));
}
// (+i)*v = (-im, re)
__device__ __forceinline__ ull mpos_i(ull v)
{
    float r, i; unpack2(v, r, i);
    return pack2(fneg(i), r);
}
// real scalar * complex
__device__ __forceinline__ ull cscale(ull v, float f) { return cmul2(pack2(f, f), v); }

__device__ __forceinline__ ull shfl64(ull v, int m)
{
    return __shfl_xor_sync(0xffffffffu, v, m);
}

// ---------------------------------------------------------------------------
// Packed 8-point complex FFT. fwd=true: e^{-i}, false: e^{+i}. NO scaling.
// Value-identical to the scalar version (adds/subs/muls on the same pairs).
// ---------------------------------------------------------------------------
__device__ __forceinline__ void cfft8p(ull z[8], const bool fwd)
{
    const float cc = 0.70710678118654752440f;
    ull t0 = cadd(z[0], z[4]);
    ull t1 = csub(z[0], z[4]);
    ull t2 = cadd(z[2], z[6]);
    ull t3 = csub(z[2], z[6]);
    ull E0 = cadd(t0, t2);
    ull E2 = csub(t0, t2);
    ull w3 = fwd ? mneg_i(t3) : mpos_i(t3);
    ull E1 = cadd(t1, w3);
    ull E3 = csub(t1, w3);
    ull u0 = cadd(z[1], z[5]);
    ull u1 = csub(z[1], z[5]);
    ull u2 = cadd(z[3], z[7]);
    ull u3 = csub(z[3], z[7]);
    ull O0 = cadd(u0, u2);
    ull O2 = csub(u0, u2);
    ull wu = fwd ? mneg_i(u3) : mpos_i(u3);
    ull O1 = cadd(u1, wu);
    ull O3 = csub(u1, wu);
    ull T0 = O0;
    ull s1 = fwd ? mneg_i(O1) : mpos_i(O1);
    ull T1 = cscale(cadd(O1, s1), cc);
    ull T2 = fwd ? mneg_i(O2) : mpos_i(O2);
    ull s3 = fwd ? mneg_i(O3) : mpos_i(O3);
    ull T3 = cscale(csub(s3, O3), cc);
    z[0] = cadd(E0, T0); z[4] = csub(E0, T0);
    z[1] = cadd(E1, T1); z[5] = csub(E1, T1);
    z[2] = cadd(E2, T2); z[6] = csub(E2, T2);
    z[3] = cadd(E3, T3); z[7] = csub(E3, T3);
}

// tile decode: t in [0, 2048): b = t>>9, ph = (t>>4)&31, pw16 = t&15
#define NT_TILES 2048

// ---------------------------------------------------------------------------
// Kernel F6 (512 threads, persistent): r11 pipeline with the FFT phase fully
// converted to packed f32x2 complex arithmetic (swizzles on the alu pipe).
// smem: sWT 16384 fl | sFilt 5248 fl | sIn 16384 fl | sMid(half) 17408 fl
// ---------------------------------------------------------------------------
__global__ void __launch_bounds__(512, 1) kF6(const float* __restrict__ img,
                                              const float* __restrict__ evt,
                                              const float* __restrict__ w_img,
                                              const float* __restrict__ w_evt,
                                              const float* __restrict__ filt)
{
    extern __shared__ float sm[];
    float*  sWT   = sm;                                    // [64][256]
    float*  sFilt = sm + 16384;                            // [128][41]
    float*  sIn   = sm + 21632;                            // [2][64][128]
    __half* sMidH = reinterpret_cast<__half*>(sm + 38016); // [256][136]

    const int tid    = threadIdx.x;
    const int stride = gridDim.x;

    const float4* img4 = reinterpret_cast<const float4*>(img);
    const float4* evt4 = reinterpret_cast<const float4*>(evt);

    // one-time prologue: weights (transposed) + filter
    for (int i = tid; i < 64 * 128; i += 512) {
        int k = i >> 7, o = i & 127;
        sWT[k * 256 + o]       = w_img[o * 64 + k];
        sWT[k * 256 + 128 + o] = w_evt[o * 64 + k];
    }
    for (int i = tid; i < 128 * 40; i += 512) {
        int o = i / 40, j = i - o * 40;
        sFilt[o * 41 + j] = filt[i];
    }

    int t = blockIdx.x;
    if (t < NT_TILES) {
        const int b0 = t >> 9, ph0 = (t >> 4) & 31, pw0 = t & 15;
        for (int i = tid; i < 64 * 32; i += 512) {
            int c = i >> 5, q4 = i & 31;
            int r = q4 >> 2, xx = q4 & 3;
            int g4 = (((b0 * 64 + c) * 256 + ph0 * 8 + r) * 256 + pw0 * 16) / 4 + xx;
            *reinterpret_cast<float4*>(&sIn[c * 128 + q4 * 4])        = img4[g4];
            *reinterpret_cast<float4*>(&sIn[8192 + c * 128 + q4 * 4]) = evt4[g4];
        }
    }
    __syncthreads();

    // GEMM thread tile: 8 slots x 8 px
    const int rb = tid >> 4, cb = tid & 15;
    const int r0 = rb * 8, c0 = cb * 8;
    const float* pin = sIn + ((r0 >= 128) ? 8192 : 0);

    // FFT role: 2 threads per (channel, patch)
    const int lane = tid & 31;
    const int w    = tid >> 5;
    const int h    = lane >> 4;
    const int item = w * 16 + (lane & 15);
    const int o    = item & 127;
    const int pp   = item >> 7;
    const bool hB  = (h == 1);
    const float C7 = 0.70710678118654752440f;
    const __half* rowI = sMidH + o * 136 + pp * 8;
    const __half* rowE = sMidH + (128 + o) * 136 + pp * 8;
    const float* fo = sFilt + o * 41;

    const ull C7P  = pack2(C7, C7);
    const ull NC7P = pack2(-C7, -C7);
    const ull HALF = pack2(0.5f, 0.5f);
    const ull ONE0 = pack2(1.0f, 0.0f);
    const float HSC = 0.5f / 64.0f;   // 0.5 (hermitian split) * 1/64 (irfft2)

    while (t < NT_TILES) {
        const int b    = t >> 9;
        const int ph   = (t >> 4) & 31;
        const int pw16 = t & 15;
        const int tn   = t + stride;

        // ---- GEMM: 256 slots x 128 px, k=64 (f32x2) ----
        ull acc[32];
#pragma unroll
        for (int i = 0; i < 32; i++) acc[i] = 0ULL;
#pragma unroll 4
        for (int k = 0; k < 64; k++) {
            float4 w0 = *reinterpret_cast<const float4*>(&sWT[k * 256 + r0]);
            float4 w1 = *reinterpret_cast<const float4*>(&sWT[k * 256 + r0 + 4]);
            ulonglong2 xa = *reinterpret_cast<const ulonglong2*>(&pin[k * 128 + c0]);
            ulonglong2 xb = *reinterpret_cast<const ulonglong2*>(&pin[k * 128 + c0 + 4]);
            ull xv[4] = {xa.x, xa.y, xb.x, xb.y};
            float wf[8] = {w0.x, w0.y, w0.z, w0.w, w1.x, w1.y, w1.z, w1.w};
#pragma unroll
            for (int i = 0; i < 8; i++) {
                ull wp = pack2(wf[i], wf[i]);
#pragma unroll
                for (int j = 0; j < 4; j++)
                    acc[i * 4 + j] = fma2(wp, xv[j], acc[i * 4 + j]);
            }
        }
        __syncthreads();   // sIn reads done; prev FFT done with sMid

        // ---- spill acc -> sMid fp16 ----
#pragma unroll
        for (int i = 0; i < 8; i++) {
            __half2 hh[4];
#pragma unroll
            for (int j = 0; j < 4; j++) {
                float lo, hi;
                unpack2(acc[i * 4 + j], lo, hi);
                hh[j] = __floats2half2_rn(lo, hi);
            }
            *reinterpret_cast<uint4*>(&sMidH[(r0 + i) * 136 + c0]) =
                *reinterpret_cast<uint4*>(hh);
        }
        // ---- preload pixels for next tile ----
        if (tn < NT_TILES) {
            const int bn = tn >> 9, phn = (tn >> 4) & 31, pwn = tn & 15;
            for (int i = tid; i < 64 * 32; i += 512) {
                int c = i >> 5, q4 = i & 31;
                int r = q4 >> 2, xx = q4 & 3;
                int g4 = (((bn * 64 + c) * 256 + phn * 8 + r) * 256 + pwn * 16) / 4 + xx;
                *reinterpret_cast<float4*>(&sIn[c * 128 + q4 * 4])        = img4[g4];
                *reinterpret_cast<float4*>(&sIn[8192 + c * 128 + q4 * 4]) = evt4[g4];
            }
        }
        __syncthreads();   // sMid + sIn(next) ready

        // ---- cooperative register FFT (packed complex: lo=img-path re) ----
        ull ZP[32];   // 4 local rows x 8 cols, packed (re, im)

        // stage A: row FFTs of z = img + i*event (rows h*4 .. h*4+3)
#pragma unroll
        for (int j = 0; j < 4; j++) {
            const int R = h * 4 + j;
            uint4 ra  = *reinterpret_cast<const uint4*>(rowI + R * 16);
            uint4 rb2 = *reinterpret_cast<const uint4*>(rowE + R * 16);
            const __half2* ha = reinterpret_cast<const __half2*>(&ra);
            const __half2* hb = reinterpret_cast<const __half2*>(&rb2);
            ull z[8];
#pragma unroll
            for (int tt = 0; tt < 4; tt++) {
                float2 fa = __half22float2(ha[tt]);
                float2 fb = __half22float2(hb[tt]);
                z[2 * tt]     = pack2(fa.x, fb.x);
                z[2 * tt + 1] = pack2(fa.y, fb.y);
            }
            cfft8p(z, true);
#pragma unroll
            for (int c = 0; c < 8; c++) ZP[j * 8 + c] = z[c];
        }

        // stage B-fwd: 8-pt column FFTs, DIF split across thread pair
#pragma unroll
        for (int c = 0; c < 8; c++) {
            ull l[4], r[4];
#pragma unroll
            for (int j = 0; j < 4; j++) l[j] = ZP[j * 8 + c];
#pragma unroll
            for (int j = 0; j < 4; j++) r[j] = shfl64(l[j], 16);
            ull tq[4];
            if (!hB) {
#pragma unroll
                for (int j = 0; j < 4; j++) tq[j] = cadd(l[j], r[j]);
            } else {
                ull d[4];
#pragma unroll
                for (int j = 0; j < 4; j++) d[j] = csub(r[j], l[j]);
                tq[0] = d[0];
                tq[1] = cscale(cadd(d[1], mneg_i(d[1])), C7);
                tq[2] = mneg_i(d[2]);
                tq[3] = cscale(csub(mneg_i(d[3]), d[3]), C7);
            }
            ull s0 = cadd(tq[0], tq[2]);
            ull s1 = csub(tq[0], tq[2]);
            ull s2 = cadd(tq[1], tq[3]);
            ull s3 = csub(tq[1], tq[3]);
            ull ws = mneg_i(s3);
            ZP[0 * 8 + c] = cadd(s0, s2);
            ZP[1 * 8 + c] = cadd(s1, ws);
            ZP[2 * 8 + c] = csub(s0, s2);
            ZP[3 * 8 + c] = csub(s1, ws);
        }

        // stage B-combine+inverse (packed): pairs (v, m=(8-v)&7)
        const int vv[5] = {0, 4, 1, 2, 3};
        const int mm[5] = {0, 4, 7, 6, 5};
#pragma unroll
        for (int pidx = 0; pidx < 5; pidx++) {
            const int v = vv[pidx], m = mm[pidx];
            ull x[4];
#pragma unroll
            for (int k = 0; k < 4; k++) {
                const int u  = 2 * k + h;
                const int kn = hB ? (3 - k) : ((4 - k) & 3);
                ull p  = ZP[k * 8 + v];
                ull cq = cconj(ZP[kn * 8 + m]);
                ull I  = cadd(p, cq);                 // (pr+qr, pi-qi), x2 of scalar
                ull D  = csub(p, cq);                 // (pr-qr, pi+qi)
                ull E  = cscale(mneg_i(D), HSC * fo[u * 5 + v]);  // 0.5f/64 * (pi+qi, qr-pr)
                ull a  = fma2(HALF, I, ONE0);         // (0.5(pr+qr)+1, 0.5(pi-qi))
                float ar, ai;
                unpack2(a, ar, ai);
                x[k] = fma2(pack2(ar, ar), E, cmul2(pack2(ai, ai), mpos_i(E)));
            }
            // IFFT4 (e^{+i}, unscaled)
            ull s0 = cadd(x[0], x[2]);
            ull s1 = csub(x[0], x[2]);
            ull s2 = cadd(x[1], x[3]);
            ull s3 = csub(x[1], x[3]);
            ull g0 = cadd(s0, s2);
            ull g2 = csub(s0, s2);
            ull wg = mpos_i(s3);
            ull g1 = cadd(s1, wg);
            ull g3 = csub(s1, wg);
            ull h0 = shfl64(g0, 16), h1 = shfl64(g1, 16);
            ull h2 = shfl64(g2, 16), h3 = shfl64(g3, 16);
            if (!hB) {   // z_j = G_j + W^{-j} H_j
                ZP[0 * 8 + v] = cadd(g0, h0);
                ZP[1 * 8 + v] = fma2(C7P, cadd(h1, mpos_i(h1)), g1);
                ZP[2 * 8 + v] = cadd(g2, mpos_i(h2));
                ZP[3 * 8 + v] = fma2(C7P, mpos_i(cadd(h3, mpos_i(h3))), g3);
            } else {     // z_{j+4} = H_j - W^{-j} G_j
                ZP[0 * 8 + v] = csub(h0, g0);
                ZP[1 * 8 + v] = fma2(NC7P, cadd(g1, mpos_i(g1)), h1);
                ZP[2 * 8 + v] = cadd(h2, mneg_i(g2));
                ZP[3 * 8 + v] = fma2(C7P, cadd(g3, mneg_i(g3)), h3);
            }
        }

        // stage C: row inverse (hermitian extension over v), fp16 store
        // (1/64 scale already folded into E upstream)
        __half* outp = g_xmid + (((size_t)(b * 128 + o) * 256 + ph * 8) * 256
                                 + pw16 * 16 + pp * 8);
#pragma unroll
        for (int j = 0; j < 4; j++) {
            const int R = h * 4 + j;
            ull z[8];
#pragma unroll
            for (int v = 0; v < 5; v++) z[v] = ZP[j * 8 + v];
            z[5] = cconj(ZP[j * 8 + 3]);
            z[6] = cconj(ZP[j * 8 + 2]);
            z[7] = cconj(ZP[j * 8 + 1]);
            cfft8p(z, false);
            __half2 hh[4];
#pragma unroll
            for (int tt = 0; tt < 4; tt++) {
                float r0f, i0f, r1f, i1f;
                unpack2(z[2 * tt], r0f, i0f);
                unpack2(z[2 * tt + 1], r1f, i1f);
                hh[tt] = __floats2half2_rn(r0f, r1f);
            }
            *reinterpret_cast<uint4*>(outp + (size_t)R * 256) =
                *reinterpret_cast<uint4*>(hh);
        }

        t = tn;
    }
}

// ---------------------------------------------------------------------------
// Kernel DW: depthwise 3x3 (SAME) + exact GELU gate. (r9/r11 version)
// ---------------------------------------------------------------------------
__global__ void __launch_bounds__(256) kDW(const float* __restrict__ w_dw)
{
    __shared__ float sH[2 * 18 * 68];

    const int tid = threadIdx.x;
    const int b = blockIdx.z >> 6, c = blockIdx.z & 63;
    const int x0 = blockIdx.x * 64, y0 = blockIdx.y * 16;

    float w1[9], w2[9];
#pragma unroll
    for (int j = 0; j < 9; j++) {
        w1[j] = w_dw[c * 9 + j];
        w2[j] = w_dw[(c + 64) * 9 + j];
    }

    const __half* src0 = g_xmid + (size_t)(b * 128 + c) * 65536;
    const __half* src1 = src0 + (size_t)64 * 65536;

    for (int i = tid; i < 18 * 66; i += 256) {
        int y = i / 66, x = i - y * 66;
        int gy = y0 + y - 1, gx = x0 + x - 1;
        float v0 = 0.f, v1 = 0.f;
        if (gy >= 0 && gy < 256 && gx >= 0 && gx < 256) {
            size_t gi = (size_t)gy * 256 + gx;
            v0 = __half2float(src0[gi]);
            v1 = __half2float(src1[gi]);
        }
        sH[y * 68 + x]        = v0;
        sH[1224 + y * 68 + x] = v1;
    }
    __syncthreads();

    const int px = tid & 63, ty = tid >> 6;
    __half* dst = g_gate + (size_t)(b * 64 + c) * 65536;
#pragma unroll
    for (int yy = 0; yy < 4; yy++) {
        int py = ty * 4 + yy;
        float a = 0.f, bb = 0.f;
#pragma unroll
        for (int dy = 0; dy < 3; dy++)
#pragma unroll
            for (int dx = 0; dx < 3; dx++) {
                a  = fmaf(sH[(py + dy) * 68 + px + dx],        w1[dy * 3 + dx], a);
                bb = fmaf(sH[1224 + (py + dy) * 68 + px + dx], w2[dy * 3 + dx], bb);
            }
        float gl = 0.5f * a * (1.0f + erff(a * 0.70710678118654752f));
        dst[(size_t)(y0 + py) * 256 + x0 + px] = __float2half_rn(gl * bb);
    }
}

// ---------------------------------------------------------------------------
// Kernel Out2: persistent 1x1 projection. (r11 version)
// ---------------------------------------------------------------------------
__global__ void __launch_bounds__(256, 2) kOut2(const float* __restrict__ w_out,
                                                float* __restrict__ out)
{
    extern __shared__ float sm[];
    float* sG   = sm;          // [64][256]
    float* sWoT = sm + 16384;  // [64][64]

    const int tid    = threadIdx.x;
    const int stride = gridDim.x;

    for (int i = tid; i < 64 * 64; i += 256) {
        int k = i >> 6, o = i & 63;
        sWoT[k * 64 + o] = w_out[o * 64 + k];
    }

    const int ob = tid >> 5, pb = tid & 31;
    const int oc0 = ob * 8, p0 = pb * 8;

    for (int rr = blockIdx.x; rr < 1024; rr += stride) {
        const int b = rr >> 8, y = rr & 255;

        __syncthreads();
        for (int i = tid; i < 2048; i += 256) {
            int k = i >> 5, p8 = i & 31;
            uint4 rh = *reinterpret_cast<const uint4*>(
                g_gate + (size_t)(b * 64 + k) * 65536 + (size_t)y * 256 + p8 * 8);
            const __half2* hp = reinterpret_cast<const __half2*>(&rh);
            float v[8];
#pragma unroll
            for (int tt = 0; tt < 4; tt++) {
                float2 f2 = __half22float2(hp[tt]);
                v[2 * tt] = f2.x; v[2 * tt + 1] = f2.y;
            }
            float4 q0 = {v[0], v[1], v[2], v[3]};
            float4 q1 = {v[4], v[5], v[6], v[7]};
            *reinterpret_cast<float4*>(&sG[k * 256 + p8 * 8])     = q0;
            *reinterpret_cast<float4*>(&sG[k * 256 + p8 * 8 + 4]) = q1;
        }
        __syncthreads();

        ull acc[32];
#pragma unroll
        for (int i = 0; i < 32; i++) acc[i] = 0ULL;
#pragma unroll 8
        for (int k = 0; k < 64; k++) {
            float4 w0 = *reinterpret_cast<const float4*>(&sWoT[k * 64 + oc0]);
            float4 w1 = *reinterpret_cast<const float4*>(&sWoT[k * 64 + oc0 + 4]);
            ulonglong2 ga = *reinterpret_cast<const ulonglong2*>(&sG[k * 256 + p0]);
            ulonglong2 gb = *reinterpret_cast<const ulonglong2*>(&sG[k * 256 + p0 + 4]);
            ull gv[4] = {ga.x, ga.y, gb.x, gb.y};
            float wf[8] = {w0.x, w0.y, w0.z, w0.w, w1.x, w1.y, w1.z, w1.w};
#pragma unroll
            for (int i = 0; i < 8; i++) {
                ull wp = pack2(wf[i], wf[i]);
#pragma unroll
                for (int j = 0; j < 4; j++)
                    acc[i * 4 + j] = fma2(wp, gv[j], acc[i * 4 + j]);
            }
        }
#pragma unroll
        for (int i = 0; i < 8; i++) {
            float v[8];
#pragma unroll
            for (int j = 0; j < 4; j++) unpack2(acc[i * 4 + j], v[2 * j], v[2 * j + 1]);
            size_t ga = ((size_t)(b * 64 + oc0 + i) * 256 + y) * 256 + p0;
            float4 q0 = {v[0], v[1], v[2], v[3]};
            float4 q1 = {v[4], v[5], v[6], v[7]};
            *reinterpret_cast<float4*>(&out[ga])     = q0;
            *reinterpret_cast<float4*>(&out[ga + 4]) = q1;
        }
    }
}

// ---------------------------------------------------------------------------
extern "C" void kernel_launch(void* const* d_in, const int* in_sizes, int n_in,
                              void* d_out, int out_size)
{
    const float* img   = (const float*)d_in[0];
    const float* evt   = (const float*)d_in[1];
    const float* w_img = (const float*)d_in[2];
    const float* w_evt = (const float*)d_in[3];
    const float* w_dw  = (const float*)d_in[4];
    const float* filt  = (const float*)d_in[5];
    const float* w_out = (const float*)d_in[6];
    float* out = (float*)d_out;

    const int smemF = 55424 * 4;   // 221,696 B -> 1 block/SM
    const int smemO = 20480 * 4;   //  81,920 B -> 2 blocks/SM
    cudaFuncSetAttribute(kF6,   cudaFuncAttributeMaxDynamicSharedMemorySize, smemF);
    cudaFuncSetAttribute(kOut2, cudaFuncAttributeMaxDynamicSharedMemorySize, smemO);

    kF6<<<296, 512, smemF>>>(img, evt, w_img, w_evt, filt);
    kDW<<<dim3(4, 16, 256), 256>>>(w_dw);
    kOut2<<<296, 256, smemO>>>(w_out, out);
}

// round 13
// speedup vs baseline: 1.3614x; 1.0272x over previous
#include <cuda_runtime.h>
#include <cuda_fp16.h>
#include <cstdint>
#include <cmath>

// scratch: mid tensor x [4,128,256,256] fp16, gated tensor [4,64,256,256] fp16
static __device__ __align__(16) __half g_xmid[(size_t)4 * 128 * 256 * 256];
static __device__ __align__(16) __half g_gate[(size_t)4 * 64 * 256 * 256];

typedef unsigned long long ull;

// ---------------------------------------------------------------------------
// f32x2 packed helpers. Packed complex convention: lo = re, hi = im.
// ---------------------------------------------------------------------------
__device__ __forceinline__ ull pack2(float lo, float hi)
{
    ull r;
    asm("mov.b64 %0, {%1, %2};" : "=l"(r) : "f"(lo), "f"(hi));
    return r;
}
__device__ __forceinline__ void unpack2(ull v, float& lo, float& hi)
{
    asm("mov.b64 {%0, %1}, %2;" : "=f"(lo), "=f"(hi) : "l"(v));
}
__device__ __forceinline__ ull fma2(ull a, ull b, ull c)
{
    ull d;
    asm("fma.rn.f32x2 %0, %1, %2, %3;" : "=l"(d) : "l"(a), "l"(b), "l"(c));
    return d;
}
__device__ __forceinline__ ull cadd(ull a, ull b)
{
    ull d;
    asm("add.rn.f32x2 %0, %1, %2;" : "=l"(d) : "l"(a), "l"(b));
    return d;
}
__device__ __forceinline__ ull cmul2(ull a, ull b)
{
    ull d;
    asm("mul.rn.f32x2 %0, %1, %2;" : "=l"(d) : "l"(a), "l"(b));
    return d;
}
// a - b, exact (multiply by -1 is exact)
__device__ __forceinline__ ull csub(ull a, ull b)
{
    const ull NEG1 = pack2(-1.0f, -1.0f);
    return fma2(NEG1, b, a);
}
__device__ __forceinline__ float fneg(float x)
{
    return __int_as_float(__float_as_int(x) ^ 0x80000000);
}
// conj: flip sign of imag (hi) half
__device__ __forceinline__ ull cconj(ull v) { return v ^ 0x8000000000000000ULL; }
// (-i)*v = (im, -re)
__device__ __forceinline__ ull mneg_i(ull v)
{
    float r, i; unpack2(v, r, i);
    return pack2(i, fneg(r));
}
// (+i)*v = (-im, re)
__device__ __forceinline__ ull mpos_i(ull v)
{
    float r, i; unpack2(v, r, i);
    return pack2(fneg(i), r);
}
// real scalar * complex
__device__ __forceinline__ ull cscale(ull v, float f) { return cmul2(pack2(f, f), v); }

__device__ __forceinline__ ull shfl64(ull v, int m)
{
    return __shfl_xor_sync(0xffffffffu, v, m);
}

// ---------------------------------------------------------------------------
// Packed 8-point complex FFT. fwd=true: e^{-i}, false: e^{+i}. NO scaling.
// ---------------------------------------------------------------------------
__device__ __forceinline__ void cfft8p(ull z[8], const bool fwd)
{
    const float cc = 0.70710678118654752440f;
    ull t0 = cadd(z[0], z[4]);
    ull t1 = csub(z[0], z[4]);
    ull t2 = cadd(z[2], z[6]);
    ull t3 = csub(z[2], z[6]);
    ull E0 = cadd(t0, t2);
    ull E2 = csub(t0, t2);
    ull w3 = fwd ? mneg_i(t3) : mpos_i(t3);
    ull E1 = cadd(t1, w3);
    ull E3 = csub(t1, w3);
    ull u0 = cadd(z[1], z[5]);
    ull u1 = csub(z[1], z[5]);
    ull u2 = cadd(z[3], z[7]);
    ull u3 = csub(z[3], z[7]);
    ull O0 = cadd(u0, u2);
    ull O2 = csub(u0, u2);
    ull wu = fwd ? mneg_i(u3) : mpos_i(u3);
    ull O1 = cadd(u1, wu);
    ull O3 = csub(u1, wu);
    ull T0 = O0;
    ull s1 = fwd ? mneg_i(O1) : mpos_i(O1);
    ull T1 = cscale(cadd(O1, s1), cc);
    ull T2 = fwd ? mneg_i(O2) : mpos_i(O2);
    ull s3 = fwd ? mneg_i(O3) : mpos_i(O3);
    ull T3 = cscale(csub(s3, O3), cc);
    z[0] = cadd(E0, T0); z[4] = csub(E0, T0);
    z[1] = cadd(E1, T1); z[5] = csub(E1, T1);
    z[2] = cadd(E2, T2); z[6] = csub(E2, T2);
    z[3] = cadd(E3, T3); z[7] = csub(E3, T3);
}

// tile decode: t in [0, 2048): b = t>>9, ph = (t>>4)&31, pw16 = t&15
#define NT_TILES 2048

// ---------------------------------------------------------------------------
// Kernel F7 (512 threads, persistent): r12 pipeline + register-pipelined
// pixel loads in the GEMM + scale folded into the staged filter.
// smem: sWT 16384 fl | sFilt 5248 fl | sIn 16384 fl | sMid(half) 17408 fl
// ---------------------------------------------------------------------------
__global__ void __launch_bounds__(512, 1) kF7(const float* __restrict__ img,
                                              const float* __restrict__ evt,
                                              const float* __restrict__ w_img,
                                              const float* __restrict__ w_evt,
                                              const float* __restrict__ filt)
{
    extern __shared__ float sm[];
    float*  sWT   = sm;                                    // [64][256]
    float*  sFilt = sm + 16384;                            // [128][41]
    float*  sIn   = sm + 21632;                            // [2][64][128]
    __half* sMidH = reinterpret_cast<__half*>(sm + 38016); // [256][136]

    const int tid    = threadIdx.x;
    const int stride = gridDim.x;
    const float HSC = 0.5f / 64.0f;   // 0.5 (hermitian split) * 1/64 (irfft2)

    const float4* img4 = reinterpret_cast<const float4*>(img);
    const float4* evt4 = reinterpret_cast<const float4*>(evt);

    // one-time prologue: weights (transposed) + pre-scaled filter
    for (int i = tid; i < 64 * 128; i += 512) {
        int k = i >> 7, o = i & 127;
        sWT[k * 256 + o]       = w_img[o * 64 + k];
        sWT[k * 256 + 128 + o] = w_evt[o * 64 + k];
    }
    for (int i = tid; i < 128 * 40; i += 512) {
        int o = i / 40, j = i - o * 40;
        sFilt[o * 41 + j] = filt[i] * HSC;
    }

    int t = blockIdx.x;
    if (t < NT_TILES) {
        const int b0 = t >> 9, ph0 = (t >> 4) & 31, pw0 = t & 15;
        for (int i = tid; i < 64 * 32; i += 512) {
            int c = i >> 5, q4 = i & 31;
            int r = q4 >> 2, xx = q4 & 3;
            int g4 = (((b0 * 64 + c) * 256 + ph0 * 8 + r) * 256 + pw0 * 16) / 4 + xx;
            *reinterpret_cast<float4*>(&sIn[c * 128 + q4 * 4])        = img4[g4];
            *reinterpret_cast<float4*>(&sIn[8192 + c * 128 + q4 * 4]) = evt4[g4];
        }
    }
    __syncthreads();

    // GEMM thread tile: 8 slots x 8 px
    const int rb = tid >> 4, cb = tid & 15;
    const int r0 = rb * 8, c0 = cb * 8;
    const float* pin = sIn + ((r0 >= 128) ? 8192 : 0);

    // FFT role: 2 threads per (channel, patch)
    const int lane = tid & 31;
    const int w    = tid >> 5;
    const int h    = lane >> 4;
    const int item = w * 16 + (lane & 15);
    const int o    = item & 127;
    const int pp   = item >> 7;
    const bool hB  = (h == 1);
    const float C7 = 0.70710678118654752440f;
    const __half* rowI = sMidH + o * 136 + pp * 8;
    const __half* rowE = sMidH + (128 + o) * 136 + pp * 8;
    const float* fo = sFilt + o * 41;

    const ull C7P  = pack2(C7, C7);
    const ull NC7P = pack2(-C7, -C7);
    const ull HALF = pack2(0.5f, 0.5f);
    const ull ONE0 = pack2(1.0f, 0.0f);

    while (t < NT_TILES) {
        const int b    = t >> 9;
        const int ph   = (t >> 4) & 31;
        const int pw16 = t & 15;
        const int tn   = t + stride;

        // ---- GEMM: 256 slots x 128 px, k=64 (f32x2), pipelined pixel loads
        ull acc[32];
#pragma unroll
        for (int i = 0; i < 32; i++) acc[i] = 0ULL;
        ulonglong2 xa = *reinterpret_cast<const ulonglong2*>(&pin[c0]);
        ulonglong2 xb = *reinterpret_cast<const ulonglong2*>(&pin[c0 + 4]);
#pragma unroll 4
        for (int k = 0; k < 64; k++) {
            ulonglong2 nxa, nxb;
            if (k < 63) {
                nxa = *reinterpret_cast<const ulonglong2*>(&pin[(k + 1) * 128 + c0]);
                nxb = *reinterpret_cast<const ulonglong2*>(&pin[(k + 1) * 128 + c0 + 4]);
            }
            float4 w0 = *reinterpret_cast<const float4*>(&sWT[k * 256 + r0]);
            float4 w1 = *reinterpret_cast<const float4*>(&sWT[k * 256 + r0 + 4]);
            ull xv[4] = {xa.x, xa.y, xb.x, xb.y};
            float wf[8] = {w0.x, w0.y, w0.z, w0.w, w1.x, w1.y, w1.z, w1.w};
#pragma unroll
            for (int i = 0; i < 8; i++) {
                ull wp = pack2(wf[i], wf[i]);
#pragma unroll
                for (int j = 0; j < 4; j++)
                    acc[i * 4 + j] = fma2(wp, xv[j], acc[i * 4 + j]);
            }
            xa = nxa; xb = nxb;
        }
        __syncthreads();   // sIn reads done; prev FFT done with sMid

        // ---- spill acc -> sMid fp16 ----
#pragma unroll
        for (int i = 0; i < 8; i++) {
            __half2 hh[4];
#pragma unroll
            for (int j = 0; j < 4; j++) {
                float lo, hi;
                unpack2(acc[i * 4 + j], lo, hi);
                hh[j] = __floats2half2_rn(lo, hi);
            }
            *reinterpret_cast<uint4*>(&sMidH[(r0 + i) * 136 + c0]) =
                *reinterpret_cast<uint4*>(hh);
        }
        // ---- preload pixels for next tile ----
        if (tn < NT_TILES) {
            const int bn = tn >> 9, phn = (tn >> 4) & 31, pwn = tn & 15;
            for (int i = tid; i < 64 * 32; i += 512) {
                int c = i >> 5, q4 = i & 31;
                int r = q4 >> 2, xx = q4 & 3;
                int g4 = (((bn * 64 + c) * 256 + phn * 8 + r) * 256 + pwn * 16) / 4 + xx;
                *reinterpret_cast<float4*>(&sIn[c * 128 + q4 * 4])        = img4[g4];
                *reinterpret_cast<float4*>(&sIn[8192 + c * 128 + q4 * 4]) = evt4[g4];
            }
        }
        __syncthreads();   // sMid + sIn(next) ready

        // ---- cooperative register FFT (packed complex) ----
        ull ZP[32];   // 4 local rows x 8 cols, packed (re, im)

        // stage A: row FFTs of z = img + i*event (rows h*4 .. h*4+3)
#pragma unroll
        for (int j = 0; j < 4; j++) {
            const int R = h * 4 + j;
            uint4 ra  = *reinterpret_cast<const uint4*>(rowI + R * 16);
            uint4 rb2 = *reinterpret_cast<const uint4*>(rowE + R * 16);
            const __half2* ha = reinterpret_cast<const __half2*>(&ra);
            const __half2* hb = reinterpret_cast<const __half2*>(&rb2);
            ull z[8];
#pragma unroll
            for (int tt = 0; tt < 4; tt++) {
                float2 fa = __half22float2(ha[tt]);
                float2 fb = __half22float2(hb[tt]);
                z[2 * tt]     = pack2(fa.x, fb.x);
                z[2 * tt + 1] = pack2(fa.y, fb.y);
            }
            cfft8p(z, true);
#pragma unroll
            for (int c = 0; c < 8; c++) ZP[j * 8 + c] = z[c];
        }

        // stage B-fwd: 8-pt column FFTs, DIF split across thread pair
#pragma unroll
        for (int c = 0; c < 8; c++) {
            ull l[4], r[4];
#pragma unroll
            for (int j = 0; j < 4; j++) l[j] = ZP[j * 8 + c];
#pragma unroll
            for (int j = 0; j < 4; j++) r[j] = shfl64(l[j], 16);
            ull tq[4];
            if (!hB) {
#pragma unroll
                for (int j = 0; j < 4; j++) tq[j] = cadd(l[j], r[j]);
            } else {
                ull d[4];
#pragma unroll
                for (int j = 0; j < 4; j++) d[j] = csub(r[j], l[j]);
                tq[0] = d[0];
                tq[1] = cscale(cadd(d[1], mneg_i(d[1])), C7);
                tq[2] = mneg_i(d[2]);
                tq[3] = cscale(csub(mneg_i(d[3]), d[3]), C7);
            }
            ull s0 = cadd(tq[0], tq[2]);
            ull s1 = csub(tq[0], tq[2]);
            ull s2 = cadd(tq[1], tq[3]);
            ull s3 = csub(tq[1], tq[3]);
            ull ws = mneg_i(s3);
            ZP[0 * 8 + c] = cadd(s0, s2);
            ZP[1 * 8 + c] = cadd(s1, ws);
            ZP[2 * 8 + c] = csub(s0, s2);
            ZP[3 * 8 + c] = csub(s1, ws);
        }

        // stage B-combine+inverse (packed): pairs (v, m=(8-v)&7)
        const int vv[5] = {0, 4, 1, 2, 3};
        const int mm[5] = {0, 4, 7, 6, 5};
#pragma unroll
        for (int pidx = 0; pidx < 5; pidx++) {
            const int v = vv[pidx], m = mm[pidx];
            ull x[4];
#pragma unroll
            for (int k = 0; k < 4; k++) {
                const int u  = 2 * k + h;
                const int kn = hB ? (3 - k) : ((4 - k) & 3);
                ull p  = ZP[k * 8 + v];
                ull cq = cconj(ZP[kn * 8 + m]);
                ull I  = cadd(p, cq);
                ull D  = csub(p, cq);
                ull E  = cscale(mneg_i(D), fo[u * 5 + v]);   // filter pre-scaled
                ull a  = fma2(HALF, I, ONE0);
                float ar, ai;
                unpack2(a, ar, ai);
                x[k] = fma2(pack2(ar, ar), E, cmul2(pack2(ai, ai), mpos_i(E)));
            }
            ull s0 = cadd(x[0], x[2]);
            ull s1 = csub(x[0], x[2]);
            ull s2 = cadd(x[1], x[3]);
            ull s3 = csub(x[1], x[3]);
            ull g0 = cadd(s0, s2);
            ull g2 = csub(s0, s2);
            ull wg = mpos_i(s3);
            ull g1 = cadd(s1, wg);
            ull g3 = csub(s1, wg);
            ull h0 = shfl64(g0, 16), h1 = shfl64(g1, 16);
            ull h2 = shfl64(g2, 16), h3 = shfl64(g3, 16);
            if (!hB) {   // z_j = G_j + W^{-j} H_j
                ZP[0 * 8 + v] = cadd(g0, h0);
                ZP[1 * 8 + v] = fma2(C7P, cadd(h1, mpos_i(h1)), g1);
                ZP[2 * 8 + v] = cadd(g2, mpos_i(h2));
                ZP[3 * 8 + v] = fma2(C7P, mpos_i(cadd(h3, mpos_i(h3))), g3);
            } else {     // z_{j+4} = H_j - W^{-j} G_j
                ZP[0 * 8 + v] = csub(h0, g0);
                ZP[1 * 8 + v] = fma2(NC7P, cadd(g1, mpos_i(g1)), h1);
                ZP[2 * 8 + v] = cadd(h2, mneg_i(g2));
                ZP[3 * 8 + v] = fma2(C7P, cadd(g3, mneg_i(g3)), h3);
            }
        }

        // stage C: row inverse (hermitian extension over v), fp16 store
        __half* outp = g_xmid + (((size_t)(b * 128 + o) * 256 + ph * 8) * 256
                                 + pw16 * 16 + pp * 8);
#pragma unroll
        for (int j = 0; j < 4; j++) {
            const int R = h * 4 + j;
            ull z[8];
#pragma unroll
            for (int v = 0; v < 5; v++) z[v] = ZP[j * 8 + v];
            z[5] = cconj(ZP[j * 8 + 3]);
            z[6] = cconj(ZP[j * 8 + 2]);
            z[7] = cconj(ZP[j * 8 + 1]);
            cfft8p(z, false);
            __half2 hh[4];
#pragma unroll
            for (int tt = 0; tt < 4; tt++) {
                float r0f, i0f, r1f, i1f;
                unpack2(z[2 * tt], r0f, i0f);
                unpack2(z[2 * tt + 1], r1f, i1f);
                hh[tt] = __floats2half2_rn(r0f, r1f);
            }
            *reinterpret_cast<uint4*>(outp + (size_t)R * 256) =
                *reinterpret_cast<uint4*>(hh);
        }

        t = tn;
    }
}

// ---------------------------------------------------------------------------
// Kernel DW2: depthwise 3x3 (SAME) + exact GELU gate, vectorized fp16 halo.
// smem: sH2 [2][18][80] halves = 11,520 B (static)
// ---------------------------------------------------------------------------
__global__ void __launch_bounds__(256) kDW2(const float* __restrict__ w_dw)
{
    __shared__ __half sH2[2 * 18 * 80];

    const int tid = threadIdx.x;
    const int b = blockIdx.z >> 6, c = blockIdx.z & 63;
    const int x0 = blockIdx.x * 64, y0 = blockIdx.y * 16;

    float w1[9], w2[9];
#pragma unroll
    for (int j = 0; j < 9; j++) {
        w1[j] = w_dw[c * 9 + j];
        w2[j] = w_dw[(c + 64) * 9 + j];
    }

    const __half* src0 = g_xmid + (size_t)(b * 128 + c) * 65536;
    const __half* src1 = src0 + (size_t)64 * 65536;
    const __half zeroh = __float2half(0.f);

    // halo: per channel 18 rows x 10 chunks of 8 halves covering gx in
    // [x0-8, x0+72). Conv taps live at smem x index (px+dx) + 7 in [7,72].
    for (int i = tid; i < 360; i += 256) {
        const int ch  = i / 180;
        const int rem = i - ch * 180;
        const int y = rem / 10, chk = rem - y * 10;
        const int gy = y0 + y - 1;
        const int gxc = x0 - 8 + chk * 8;
        uint4 v = make_uint4(0u, 0u, 0u, 0u);
        if (gy >= 0 && gy < 256) {
            const __half* src = (ch ? src1 : src0) + (size_t)gy * 256;
            if (gxc >= 0 && gxc + 8 <= 256) {
                v = *reinterpret_cast<const uint4*>(src + gxc);
            } else {
                __half2 h2[4];
#pragma unroll
                for (int e = 0; e < 4; e++) {
                    int g0 = gxc + 2 * e, g1 = g0 + 1;
                    __half a = (g0 >= 0 && g0 < 256) ? src[g0] : zeroh;
                    __half d = (g1 >= 0 && g1 < 256) ? src[g1] : zeroh;
                    h2[e] = __halves2half2(a, d);
                }
                v = *reinterpret_cast<uint4*>(h2);
            }
        }
        *reinterpret_cast<uint4*>(&sH2[ch * 1440 + y * 80 + chk * 8]) = v;
    }
    __syncthreads();

    const int px = tid & 63, ty = tid >> 6;
    __half* dst = g_gate + (size_t)(b * 64 + c) * 65536;
#pragma unroll
    for (int yy = 0; yy < 4; yy++) {
        int py = ty * 4 + yy;
        float a = 0.f, bb = 0.f;
#pragma unroll
        for (int dy = 0; dy < 3; dy++)
#pragma unroll
            for (int dx = 0; dx < 3; dx++) {
                const int hoff = (py + dy) * 80 + px + dx + 7;
                a  = fmaf(__half2float(sH2[hoff]),        w1[dy * 3 + dx], a);
                bb = fmaf(__half2float(sH2[1440 + hoff]), w2[dy * 3 + dx], bb);
            }
        float gl = 0.5f * a * (1.0f + erff(a * 0.70710678118654752f));
        dst[(size_t)(y0 + py) * 256 + x0 + px] = __float2half_rn(gl * bb);
    }
}

// ---------------------------------------------------------------------------
// Kernel Out3: persistent 1x1 projection with pipelined gate loads.
// smem: sG[64][256] fp32 + sWoT[64][64] = 81,920 B (2 blocks/SM)
// ---------------------------------------------------------------------------
__global__ void __launch_bounds__(256, 2) kOut3(const float* __restrict__ w_out,
                                                float* __restrict__ out)
{
    extern __shared__ float sm[];
    float* sG   = sm;          // [64][256]
    float* sWoT = sm + 16384;  // [64][64]

    const int tid    = threadIdx.x;
    const int stride = gridDim.x;

    for (int i = tid; i < 64 * 64; i += 256) {
        int k = i >> 6, o = i & 63;
        sWoT[k * 64 + o] = w_out[o * 64 + k];
    }

    const int ob = tid >> 5, pb = tid & 31;
    const int oc0 = ob * 8, p0 = pb * 8;

    for (int rr = blockIdx.x; rr < 1024; rr += stride) {
        const int b = rr >> 8, y = rr & 255;

        __syncthreads();   // previous GEMM's sG reads done (and weights ready)
        for (int i = tid; i < 2048; i += 256) {
            int k = i >> 5, p8 = i & 31;
            uint4 rh = *reinterpret_cast<const uint4*>(
                g_gate + (size_t)(b * 64 + k) * 65536 + (size_t)y * 256 + p8 * 8);
            const __half2* hp = reinterpret_cast<const __half2*>(&rh);
            float v[8];
#pragma unroll
            for (int tt = 0; tt < 4; tt++) {
                float2 f2 = __half22float2(hp[tt]);
                v[2 * tt] = f2.x; v[2 * tt + 1] = f2.y;
            }
            float4 q0 = {v[0], v[1], v[2], v[3]};
            float4 q1 = {v[4], v[5], v[6], v[7]};
            *reinterpret_cast<float4*>(&sG[k * 256 + p8 * 8])     = q0;
            *reinterpret_cast<float4*>(&sG[k * 256 + p8 * 8 + 4]) = q1;
        }
        __syncthreads();

        ull acc[32];
#pragma unroll
        for (int i = 0; i < 32; i++) acc[i] = 0ULL;
        ulonglong2 ga = *reinterpret_cast<const ulonglong2*>(&sG[p0]);
        ulonglong2 gb = *reinterpret_cast<const ulonglong2*>(&sG[p0 + 4]);
#pragma unroll 8
        for (int k = 0; k < 64; k++) {
            ulonglong2 nga, ngb;
            if (k < 63) {
                nga = *reinterpret_cast<const ulonglong2*>(&sG[(k + 1) * 256 + p0]);
                ngb = *reinterpret_cast<const ulonglong2*>(&sG[(k + 1) * 256 + p0 + 4]);
            }
            float4 w0 = *reinterpret_cast<const float4*>(&sWoT[k * 64 + oc0]);
            float4 w1 = *reinterpret_cast<const float4*>(&sWoT[k * 64 + oc0 + 4]);
            ull gv[4] = {ga.x, ga.y, gb.x, gb.y};
            float wf[8] = {w0.x, w0.y, w0.z, w0.w, w1.x, w1.y, w1.z, w1.w};
#pragma unroll
            for (int i = 0; i < 8; i++) {
                ull wp = pack2(wf[i], wf[i]);
#pragma unroll
                for (int j = 0; j < 4; j++)
                    acc[i * 4 + j] = fma2(wp, gv[j], acc[i * 4 + j]);
            }
            ga = nga; gb = ngb;
        }
#pragma unroll
        for (int i = 0; i < 8; i++) {
            float v[8];
#pragma unroll
            for (int j = 0; j < 4; j++) unpack2(acc[i * 4 + j], v[2 * j], v[2 * j + 1]);
            size_t gaddr = ((size_t)(b * 64 + oc0 + i) * 256 + y) * 256 + p0;
            float4 q0 = {v[0], v[1], v[2], v[3]};
            float4 q1 = {v[4], v[5], v[6], v[7]};
            *reinterpret_cast<float4*>(&out[gaddr])     = q0;
            *reinterpret_cast<float4*>(&out[gaddr + 4]) = q1;
        }
    }
}

// ---------------------------------------------------------------------------
extern "C" void kernel_launch(void* const* d_in, const int* in_sizes, int n_in,
                              void* d_out, int out_size)
{
    const float* img   = (const float*)d_in[0];
    const float* evt   = (const float*)d_in[1];
    const float* w_img = (const float*)d_in[2];
    const float* w_evt = (const float*)d_in[3];
    const float* w_dw  = (const float*)d_in[4];
    const float* filt  = (const float*)d_in[5];
    const float* w_out = (const float*)d_in[6];
    float* out = (float*)d_out;

    const int smemF = 55424 * 4;   // 221,696 B -> 1 block/SM
    const int smemO = 20480 * 4;   //  81,920 B -> 2 blocks/SM
    cudaFuncSetAttribute(kF7,   cudaFuncAttributeMaxDynamicSharedMemorySize, smemF);
    cudaFuncSetAttribute(kOut3, cudaFuncAttributeMaxDynamicSharedMemorySize, smemO);

    kF7<<<296, 512, smemF>>>(img, evt, w_img, w_evt, filt);
    kDW2<<<dim3(4, 16, 256), 256>>>(w_dw);
    kOut3<<<296, 256, smemO>>>(w_out, out);
}

// round 14
// speedup vs baseline: 1.3634x; 1.0014x over previous
#include <cuda_runtime.h>
#include <cuda_fp16.h>
#include <cstdint>
#include <cmath>

// scratch: mid tensor x [4,128,256,256] fp16, gated tensor [4,64,256,256] fp16
static __device__ __align__(16) __half g_xmid[(size_t)4 * 128 * 256 * 256];
static __device__ __align__(16) __half g_gate[(size_t)4 * 64 * 256 * 256];

typedef unsigned long long ull;

// ---------------------------------------------------------------------------
// f32x2 packed helpers. Packed complex convention: lo = re, hi = im.
// ---------------------------------------------------------------------------
__device__ __forceinline__ ull pack2(float lo, float hi)
{
    ull r;
    asm("mov.b64 %0, {%1, %2};" : "=l"(r) : "f"(lo), "f"(hi));
    return r;
}
__device__ __forceinline__ void unpack2(ull v, float& lo, float& hi)
{
    asm("mov.b64 {%0, %1}, %2;" : "=f"(lo), "=f"(hi) : "l"(v));
}
__device__ __forceinline__ ull fma2(ull a, ull b, ull c)
{
    ull d;
    asm("fma.rn.f32x2 %0, %1, %2, %3;" : "=l"(d) : "l"(a), "l"(b), "l"(c));
    return d;
}
__device__ __forceinline__ ull cadd(ull a, ull b)
{
    ull d;
    asm("add.rn.f32x2 %0, %1, %2;" : "=l"(d) : "l"(a), "l"(b));
    return d;
}
__device__ __forceinline__ ull cmul2(ull a, ull b)
{
    ull d;
    asm("mul.rn.f32x2 %0, %1, %2;" : "=l"(d) : "l"(a), "l"(b));
    return d;
}
// a - b, exact (multiply by -1 is exact)
__device__ __forceinline__ ull csub(ull a, ull b)
{
    const ull NEG1 = pack2(-1.0f, -1.0f);
    return fma2(NEG1, b, a);
}
__device__ __forceinline__ float fneg(float x)
{
    return __int_as_float(__float_as_int(x) ^ 0x80000000);
}
// conj: flip sign of imag (hi) half
__device__ __forceinline__ ull cconj(ull v) { return v ^ 0x8000000000000000ULL; }
// (-i)*v = (im, -re)
__device__ __forceinline__ ull mneg_i(ull v)
{
    float r, i; unpack2(v, r, i);
    return pack2(i, fneg(r));
}
// (+i)*v = (-im, re)
__device__ __forceinline__ ull mpos_i(ull v)
{
    float r, i; unpack2(v, r, i);
    return pack2(fneg(i), r);
}
// real scalar * complex
__device__ __forceinline__ ull cscale(ull v, float f) { return cmul2(pack2(f, f), v); }

__device__ __forceinline__ ull shfl64(ull v, int m)
{
    return __shfl_xor_sync(0xffffffffu, v, m);
}

// ---------------------------------------------------------------------------
// Packed 8-point complex FFT. fwd=true: e^{-i}, false: e^{+i}. NO scaling.
// ---------------------------------------------------------------------------
__device__ __forceinline__ void cfft8p(ull z[8], const bool fwd)
{
    const float cc = 0.70710678118654752440f;
    ull t0 = cadd(z[0], z[4]);
    ull t1 = csub(z[0], z[4]);
    ull t2 = cadd(z[2], z[6]);
    ull t3 = csub(z[2], z[6]);
    ull E0 = cadd(t0, t2);
    ull E2 = csub(t0, t2);
    ull w3 = fwd ? mneg_i(t3) : mpos_i(t3);
    ull E1 = cadd(t1, w3);
    ull E3 = csub(t1, w3);
    ull u0 = cadd(z[1], z[5]);
    ull u1 = csub(z[1], z[5]);
    ull u2 = cadd(z[3], z[7]);
    ull u3 = csub(z[3], z[7]);
    ull O0 = cadd(u0, u2);
    ull O2 = csub(u0, u2);
    ull wu = fwd ? mneg_i(u3) : mpos_i(u3);
    ull O1 = cadd(u1, wu);
    ull O3 = csub(u1, wu);
    ull T0 = O0;
    ull s1 = fwd ? mneg_i(O1) : mpos_i(O1);
    ull T1 = cscale(cadd(O1, s1), cc);
    ull T2 = fwd ? mneg_i(O2) : mpos_i(O2);
    ull s3 = fwd ? mneg_i(O3) : mpos_i(O3);
    ull T3 = cscale(csub(s3, O3), cc);
    z[0] = cadd(E0, T0); z[4] = csub(E0, T0);
    z[1] = cadd(E1, T1); z[5] = csub(E1, T1);
    z[2] = cadd(E2, T2); z[6] = csub(E2, T2);
    z[3] = cadd(E3, T3); z[7] = csub(E3, T3);
}

// tile decode: t in [0, 2048): b = t>>9, ph = (t>>4)&31, pw16 = t&15
#define NT_TILES 2048

// ---------------------------------------------------------------------------
// Kernel F7 (512 threads, persistent): r12 pipeline + register-pipelined
// pixel loads in the GEMM + scale folded into the staged filter.
// smem: sWT 16384 fl | sFilt 5248 fl | sIn 16384 fl | sMid(half) 17408 fl
// ---------------------------------------------------------------------------
__global__ void __launch_bounds__(512, 1) kF7(const float* __restrict__ img,
                                              const float* __restrict__ evt,
                                              const float* __restrict__ w_img,
                                              const float* __restrict__ w_evt,
                                              const float* __restrict__ filt)
{
    extern __shared__ float sm[];
    float*  sWT   = sm;                                    // [64][256]
    float*  sFilt = sm + 16384;                            // [128][41]
    float*  sIn   = sm + 21632;                            // [2][64][128]
    __half* sMidH = reinterpret_cast<__half*>(sm + 38016); // [256][136]

    const int tid    = threadIdx.x;
    const int stride = gridDim.x;
    const float HSC = 0.5f / 64.0f;   // 0.5 (hermitian split) * 1/64 (irfft2)

    const float4* img4 = reinterpret_cast<const float4*>(img);
    const float4* evt4 = reinterpret_cast<const float4*>(evt);

    // one-time prologue: weights (transposed) + pre-scaled filter
    for (int i = tid; i < 64 * 128; i += 512) {
        int k = i >> 7, o = i & 127;
        sWT[k * 256 + o]       = w_img[o * 64 + k];
        sWT[k * 256 + 128 + o] = w_evt[o * 64 + k];
    }
    for (int i = tid; i < 128 * 40; i += 512) {
        int o = i / 40, j = i - o * 40;
        sFilt[o * 41 + j] = filt[i] * HSC;
    }

    int t = blockIdx.x;
    if (t < NT_TILES) {
        const int b0 = t >> 9, ph0 = (t >> 4) & 31, pw0 = t & 15;
        for (int i = tid; i < 64 * 32; i += 512) {
            int c = i >> 5, q4 = i & 31;
            int r = q4 >> 2, xx = q4 & 3;
            int g4 = (((b0 * 64 + c) * 256 + ph0 * 8 + r) * 256 + pw0 * 16) / 4 + xx;
            *reinterpret_cast<float4*>(&sIn[c * 128 + q4 * 4])        = img4[g4];
            *reinterpret_cast<float4*>(&sIn[8192 + c * 128 + q4 * 4]) = evt4[g4];
        }
    }
    __syncthreads();

    // GEMM thread tile: 8 slots x 8 px
    const int rb = tid >> 4, cb = tid & 15;
    const int r0 = rb * 8, c0 = cb * 8;
    const float* pin = sIn + ((r0 >= 128) ? 8192 : 0);

    // FFT role: 2 threads per (channel, patch)
    const int lane = tid & 31;
    const int w    = tid >> 5;
    const int h    = lane >> 4;
    const int item = w * 16 + (lane & 15);
    const int o    = item & 127;
    const int pp   = item >> 7;
    const bool hB  = (h == 1);
    const float C7 = 0.70710678118654752440f;
    const __half* rowI = sMidH + o * 136 + pp * 8;
    const __half* rowE = sMidH + (128 + o) * 136 + pp * 8;
    const float* fo = sFilt + o * 41;

    const ull C7P  = pack2(C7, C7);
    const ull NC7P = pack2(-C7, -C7);
    const ull HALF = pack2(0.5f, 0.5f);
    const ull ONE0 = pack2(1.0f, 0.0f);

    while (t < NT_TILES) {
        const int b    = t >> 9;
        const int ph   = (t >> 4) & 31;
        const int pw16 = t & 15;
        const int tn   = t + stride;

        // ---- GEMM: 256 slots x 128 px, k=64 (f32x2), pipelined pixel loads
        ull acc[32];
#pragma unroll
        for (int i = 0; i < 32; i++) acc[i] = 0ULL;
        ulonglong2 xa = *reinterpret_cast<const ulonglong2*>(&pin[c0]);
        ulonglong2 xb = *reinterpret_cast<const ulonglong2*>(&pin[c0 + 4]);
#pragma unroll 4
        for (int k = 0; k < 64; k++) {
            ulonglong2 nxa, nxb;
            if (k < 63) {
                nxa = *reinterpret_cast<const ulonglong2*>(&pin[(k + 1) * 128 + c0]);
                nxb = *reinterpret_cast<const ulonglong2*>(&pin[(k + 1) * 128 + c0 + 4]);
            }
            float4 w0 = *reinterpret_cast<const float4*>(&sWT[k * 256 + r0]);
            float4 w1 = *reinterpret_cast<const float4*>(&sWT[k * 256 + r0 + 4]);
            ull xv[4] = {xa.x, xa.y, xb.x, xb.y};
            float wf[8] = {w0.x, w0.y, w0.z, w0.w, w1.x, w1.y, w1.z, w1.w};
#pragma unroll
            for (int i = 0; i < 8; i++) {
                ull wp = pack2(wf[i], wf[i]);
#pragma unroll
                for (int j = 0; j < 4; j++)
                    acc[i * 4 + j] = fma2(wp, xv[j], acc[i * 4 + j]);
            }
            xa = nxa; xb = nxb;
        }
        __syncthreads();   // sIn reads done; prev FFT done with sMid

        // ---- spill acc -> sMid fp16 ----
#pragma unroll
        for (int i = 0; i < 8; i++) {
            __half2 hh[4];
#pragma unroll
            for (int j = 0; j < 4; j++) {
                float lo, hi;
                unpack2(acc[i * 4 + j], lo, hi);
                hh[j] = __floats2half2_rn(lo, hi);
            }
            *reinterpret_cast<uint4*>(&sMidH[(r0 + i) * 136 + c0]) =
                *reinterpret_cast<uint4*>(hh);
        }
        // ---- preload pixels for next tile ----
        if (tn < NT_TILES) {
            const int bn = tn >> 9, phn = (tn >> 4) & 31, pwn = tn & 15;
            for (int i = tid; i < 64 * 32; i += 512) {
                int c = i >> 5, q4 = i & 31;
                int r = q4 >> 2, xx = q4 & 3;
                int g4 = (((bn * 64 + c) * 256 + phn * 8 + r) * 256 + pwn * 16) / 4 + xx;
                *reinterpret_cast<float4*>(&sIn[c * 128 + q4 * 4])        = img4[g4];
                *reinterpret_cast<float4*>(&sIn[8192 + c * 128 + q4 * 4]) = evt4[g4];
            }
        }
        __syncthreads();   // sMid + sIn(next) ready

        // ---- cooperative register FFT (packed complex) ----
        ull ZP[32];   // 4 local rows x 8 cols, packed (re, im)

        // stage A: row FFTs of z = img + i*event (rows h*4 .. h*4+3)
#pragma unroll
        for (int j = 0; j < 4; j++) {
            const int R = h * 4 + j;
            uint4 ra  = *reinterpret_cast<const uint4*>(rowI + R * 16);
            uint4 rb2 = *reinterpret_cast<const uint4*>(rowE + R * 16);
            const __half2* ha = reinterpret_cast<const __half2*>(&ra);
            const __half2* hb = reinterpret_cast<const __half2*>(&rb2);
            ull z[8];
#pragma unroll
            for (int tt = 0; tt < 4; tt++) {
                float2 fa = __half22float2(ha[tt]);
                float2 fb = __half22float2(hb[tt]);
                z[2 * tt]     = pack2(fa.x, fb.x);
                z[2 * tt + 1] = pack2(fa.y, fb.y);
            }
            cfft8p(z, true);
#pragma unroll
            for (int c = 0; c < 8; c++) ZP[j * 8 + c] = z[c];
        }

        // stage B-fwd: 8-pt column FFTs, DIF split across thread pair
#pragma unroll
        for (int c = 0; c < 8; c++) {
            ull l[4], r[4];
#pragma unroll
            for (int j = 0; j < 4; j++) l[j] = ZP[j * 8 + c];
#pragma unroll
            for (int j = 0; j < 4; j++) r[j] = shfl64(l[j], 16);
            ull tq[4];
            if (!hB) {
#pragma unroll
                for (int j = 0; j < 4; j++) tq[j] = cadd(l[j], r[j]);
            } else {
                ull d[4];
#pragma unroll
                for (int j = 0; j < 4; j++) d[j] = csub(r[j], l[j]);
                tq[0] = d[0];
                tq[1] = cscale(cadd(d[1], mneg_i(d[1])), C7);
                tq[2] = mneg_i(d[2]);
                tq[3] = cscale(csub(mneg_i(d[3]), d[3]), C7);
            }
            ull s0 = cadd(tq[0], tq[2]);
            ull s1 = csub(tq[0], tq[2]);
            ull s2 = cadd(tq[1], tq[3]);
            ull s3 = csub(tq[1], tq[3]);
            ull ws = mneg_i(s3);
            ZP[0 * 8 + c] = cadd(s0, s2);
            ZP[1 * 8 + c] = cadd(s1, ws);
            ZP[2 * 8 + c] = csub(s0, s2);
            ZP[3 * 8 + c] = csub(s1, ws);
        }

        // stage B-combine+inverse (packed): pairs (v, m=(8-v)&7)
        const int vv[5] = {0, 4, 1, 2, 3};
        const int mm[5] = {0, 4, 7, 6, 5};
#pragma unroll
        for (int pidx = 0; pidx < 5; pidx++) {
            const int v = vv[pidx], m = mm[pidx];
            ull x[4];
#pragma unroll
            for (int k = 0; k < 4; k++) {
                const int u  = 2 * k + h;
                const int kn = hB ? (3 - k) : ((4 - k) & 3);
                ull p  = ZP[k * 8 + v];
                ull cq = cconj(ZP[kn * 8 + m]);
                ull I  = cadd(p, cq);
                ull D  = csub(p, cq);
                ull E  = cscale(mneg_i(D), fo[u * 5 + v]);   // filter pre-scaled
                ull a  = fma2(HALF, I, ONE0);
                float ar, ai;
                unpack2(a, ar, ai);
                x[k] = fma2(pack2(ar, ar), E, cmul2(pack2(ai, ai), mpos_i(E)));
            }
            ull s0 = cadd(x[0], x[2]);
            ull s1 = csub(x[0], x[2]);
            ull s2 = cadd(x[1], x[3]);
            ull s3 = csub(x[1], x[3]);
            ull g0 = cadd(s0, s2);
            ull g2 = csub(s0, s2);
            ull wg = mpos_i(s3);
            ull g1 = cadd(s1, wg);
            ull g3 = csub(s1, wg);
            ull h0 = shfl64(g0, 16), h1 = shfl64(g1, 16);
            ull h2 = shfl64(g2, 16), h3 = shfl64(g3, 16);
            if (!hB) {   // z_j = G_j + W^{-j} H_j
                ZP[0 * 8 + v] = cadd(g0, h0);
                ZP[1 * 8 + v] = fma2(C7P, cadd(h1, mpos_i(h1)), g1);
                ZP[2 * 8 + v] = cadd(g2, mpos_i(h2));
                ZP[3 * 8 + v] = fma2(C7P, mpos_i(cadd(h3, mpos_i(h3))), g3);
            } else {     // z_{j+4} = H_j - W^{-j} G_j
                ZP[0 * 8 + v] = csub(h0, g0);
                ZP[1 * 8 + v] = fma2(NC7P, cadd(g1, mpos_i(g1)), h1);
                ZP[2 * 8 + v] = cadd(h2, mneg_i(g2));
                ZP[3 * 8 + v] = fma2(C7P, cadd(g3, mneg_i(g3)), h3);
            }
        }

        // stage C: row inverse (hermitian extension over v), fp16 store
        __half* outp = g_xmid + (((size_t)(b * 128 + o) * 256 + ph * 8) * 256
                                 + pw16 * 16 + pp * 8);
#pragma unroll
        for (int j = 0; j < 4; j++) {
            const int R = h * 4 + j;
            ull z[8];
#pragma unroll
            for (int v = 0; v < 5; v++) z[v] = ZP[j * 8 + v];
            z[5] = cconj(ZP[j * 8 + 3]);
            z[6] = cconj(ZP[j * 8 + 2]);
            z[7] = cconj(ZP[j * 8 + 1]);
            cfft8p(z, false);
            __half2 hh[4];
#pragma unroll
            for (int tt = 0; tt < 4; tt++) {
                float r0f, i0f, r1f, i1f;
                unpack2(z[2 * tt], r0f, i0f);
                unpack2(z[2 * tt + 1], r1f, i1f);
                hh[tt] = __floats2half2_rn(r0f, r1f);
            }
            *reinterpret_cast<uint4*>(outp + (size_t)R * 256) =
                *reinterpret_cast<uint4*>(hh);
        }

        t = tn;
    }
}

// ---------------------------------------------------------------------------
// Kernel DW2: depthwise 3x3 (SAME) + exact GELU gate, vectorized fp16 halo.
// smem: sH2 [2][18][80] halves = 11,520 B (static)
// ---------------------------------------------------------------------------
__global__ void __launch_bounds__(256) kDW2(const float* __restrict__ w_dw)
{
    __shared__ __half sH2[2 * 18 * 80];

    const int tid = threadIdx.x;
    const int b = blockIdx.z >> 6, c = blockIdx.z & 63;
    const int x0 = blockIdx.x * 64, y0 = blockIdx.y * 16;

    float w1[9], w2[9];
#pragma unroll
    for (int j = 0; j < 9; j++) {
        w1[j] = w_dw[c * 9 + j];
        w2[j] = w_dw[(c + 64) * 9 + j];
    }

    const __half* src0 = g_xmid + (size_t)(b * 128 + c) * 65536;
    const __half* src1 = src0 + (size_t)64 * 65536;
    const __half zeroh = __float2half(0.f);

    // halo: per channel 18 rows x 10 chunks of 8 halves covering gx in
    // [x0-8, x0+72). Conv taps live at smem x index (px+dx) + 7 in [7,72].
    for (int i = tid; i < 360; i += 256) {
        const int ch  = i / 180;
        const int rem = i - ch * 180;
        const int y = rem / 10, chk = rem - y * 10;
        const int gy = y0 + y - 1;
        const int gxc = x0 - 8 + chk * 8;
        uint4 v = make_uint4(0u, 0u, 0u, 0u);
        if (gy >= 0 && gy < 256) {
            const __half* src = (ch ? src1 : src0) + (size_t)gy * 256;
            if (gxc >= 0 && gxc + 8 <= 256) {
                v = *reinterpret_cast<const uint4*>(src + gxc);
            } else {
                __half2 h2[4];
#pragma unroll
                for (int e = 0; e < 4; e++) {
                    int g0 = gxc + 2 * e, g1 = g0 + 1;
                    __half a = (g0 >= 0 && g0 < 256) ? src[g0] : zeroh;
                    __half d = (g1 >= 0 && g1 < 256) ? src[g1] : zeroh;
                    h2[e] = __halves2half2(a, d);
                }
                v = *reinterpret_cast<uint4*>(h2);
            }
        }
        *reinterpret_cast<uint4*>(&sH2[ch * 1440 + y * 80 + chk * 8]) = v;
    }
    __syncthreads();

    const int px = tid & 63, ty = tid >> 6;
    __half* dst = g_gate + (size_t)(b * 64 + c) * 65536;
#pragma unroll
    for (int yy = 0; yy < 4; yy++) {
        int py = ty * 4 + yy;
        float a = 0.f, bb = 0.f;
#pragma unroll
        for (int dy = 0; dy < 3; dy++)
#pragma unroll
            for (int dx = 0; dx < 3; dx++) {
                const int hoff = (py + dy) * 80 + px + dx + 7;
                a  = fmaf(__half2float(sH2[hoff]),        w1[dy * 3 + dx], a);
                bb = fmaf(__half2float(sH2[1440 + hoff]), w2[dy * 3 + dx], bb);
            }
        float gl = 0.5f * a * (1.0f + erff(a * 0.70710678118654752f));
        dst[(size_t)(y0 + py) * 256 + x0 + px] = __float2half_rn(gl * bb);
    }
}

// ---------------------------------------------------------------------------
// Kernel Out3: persistent 1x1 projection with pipelined gate loads.
// smem: sG[64][256] fp32 + sWoT[64][64] = 81,920 B (2 blocks/SM)
// ---------------------------------------------------------------------------
__global__ void __launch_bounds__(256, 2) kOut3(const float* __restrict__ w_out,
                                                float* __restrict__ out)
{
    extern __shared__ float sm[];
    float* sG   = sm;          // [64][256]
    float* sWoT = sm + 16384;  // [64][64]

    const int tid    = threadIdx.x;
    const int stride = gridDim.x;

    for (int i = tid; i < 64 * 64; i += 256) {
        int k = i >> 6, o = i & 63;
        sWoT[k * 64 + o] = w_out[o * 64 + k];
    }

    const int ob = tid >> 5, pb = tid & 31;
    const int oc0 = ob * 8, p0 = pb * 8;

    for (int rr = blockIdx.x; rr < 1024; rr += stride) {
        const int b = rr >> 8, y = rr & 255;

        __syncthreads();   // previous GEMM's sG reads done (and weights ready)
        for (int i = tid; i < 2048; i += 256) {
            int k = i >> 5, p8 = i & 31;
            uint4 rh = *reinterpret_cast<const uint4*>(
                g_gate + (size_t)(b * 64 + k) * 65536 + (size_t)y * 256 + p8 * 8);
            const __half2* hp = reinterpret_cast<const __half2*>(&rh);
            float v[8];
#pragma unroll
            for (int tt = 0; tt < 4; tt++) {
                float2 f2 = __half22float2(hp[tt]);
                v[2 * tt] = f2.x; v[2 * tt + 1] = f2.y;
            }
            float4 q0 = {v[0], v[1], v[2], v[3]};
            float4 q1 = {v[4], v[5], v[6], v[7]};
            *reinterpret_cast<float4*>(&sG[k * 256 + p8 * 8])     = q0;
            *reinterpret_cast<float4*>(&sG[k * 256 + p8 * 8 + 4]) = q1;
        }
        __syncthreads();

        ull acc[32];
#pragma unroll
        for (int i = 0; i < 32; i++) acc[i] = 0ULL;
        ulonglong2 ga = *reinterpret_cast<const ulonglong2*>(&sG[p0]);
        ulonglong2 gb = *reinterpret_cast<const ulonglong2*>(&sG[p0 + 4]);
#pragma unroll 8
        for (int k = 0; k < 64; k++) {
            ulonglong2 nga, ngb;
            if (k < 63) {
                nga = *reinterpret_cast<const ulonglong2*>(&sG[(k + 1) * 256 + p0]);
                ngb = *reinterpret_cast<const ulonglong2*>(&sG[(k + 1) * 256 + p0 + 4]);
            }
            float4 w0 = *reinterpret_cast<const float4*>(&sWoT[k * 64 + oc0]);
            float4 w1 = *reinterpret_cast<const float4*>(&sWoT[k * 64 + oc0 + 4]);
            ull gv[4] = {ga.x, ga.y, gb.x, gb.y};
            float wf[8] = {w0.x, w0.y, w0.z, w0.w, w1.x, w1.y, w1.z, w1.w};
#pragma unroll
            for (int i = 0; i < 8; i++) {
                ull wp = pack2(wf[i], wf[i]);
#pragma unroll
                for (int j = 0; j < 4; j++)
                    acc[i * 4 + j] = fma2(wp, gv[j], acc[i * 4 + j]);
            }
            ga = nga; gb = ngb;
        }
#pragma unroll
        for (int i = 0; i < 8; i++) {
            float v[8];
#pragma unroll
            for (int j = 0; j < 4; j++) unpack2(acc[i * 4 + j], v[2 * j], v[2 * j + 1]);
            size_t gaddr = ((size_t)(b * 64 + oc0 + i) * 256 + y) * 256 + p0;
            float4 q0 = {v[0], v[1], v[2], v[3]};
            float4 q1 = {v[4], v[5], v[6], v[7]};
            *reinterpret_cast<float4*>(&out[gaddr])     = q0;
            *reinterpret_cast<float4*>(&out[gaddr + 4]) = q1;
        }
    }
}

// ---------------------------------------------------------------------------
extern "C" void kernel_launch(void* const* d_in, const int* in_sizes, int n_in,
                              void* d_out, int out_size)
{
    const float* img   = (const float*)d_in[0];
    const float* evt   = (const float*)d_in[1];
    const float* w_img = (const float*)d_in[2];
    const float* w_evt = (const float*)d_in[3];
    const float* w_dw  = (const float*)d_in[4];
    const float* filt  = (const float*)d_in[5];
    const float* w_out = (const float*)d_in[6];
    float* out = (float*)d_out;

    const int smemF = 55424 * 4;   // 221,696 B -> 1 block/SM
    const int smemO = 20480 * 4;   //  81,920 B -> 2 blocks/SM
    cudaFuncSetAttribute(kF7,   cudaFuncAttributeMaxDynamicSharedMemorySize, smemF);
    cudaFuncSetAttribute(kOut3, cudaFuncAttributeMaxDynamicSharedMemorySize, smemO);

    kF7<<<296, 512, smemF>>>(img, evt, w_img, w_evt, filt);
    kDW2<<<dim3(4, 16, 256), 256>>>(w_dw);
    kOut3<<<296, 256, smemO>>>(w_out, out);
}